// round 10
// baseline (speedup 1.0000x reference)
#include <cuda_runtime.h>
#include <cstdint>
#include <math.h>

#define NB_ 64
#define NS_ 512
#define NHID_ 256
#define NTAGS_ 9
#define LOGITS_N (NB_ * NS_ * NTAGS_)   // 294912
#define LENS_OFF LOGITS_N               // 294912
#define LL_OFF   (LOGITS_N + NB_)       // 294976

// Scratch (device globals: no allocation allowed)
__device__ float g_xzf[NB_ * NS_ * 1024];   // x @ W_f + b_f
__device__ float g_xzb[NB_ * NS_ * 1024];   // x @ W_b + b_b
__device__ float g_hf[NB_ * NS_ * NHID_];
__device__ float g_hb[NB_ * NS_ * NHID_];

// ---------------- packed f32x2 helpers (sm_103a FFMA2 path) ----------------
__device__ __forceinline__ unsigned long long pk2(float lo, float hi) {
    unsigned long long r;
    asm("mov.b64 %0, {%1, %2};" : "=l"(r) : "f"(lo), "f"(hi));
    return r;
}
__device__ __forceinline__ float2 unpk2(unsigned long long v) {
    float2 r;
    asm("mov.b64 {%0, %1}, %2;" : "=f"(r.x), "=f"(r.y) : "l"(v));
    return r;
}
__device__ __forceinline__ unsigned long long fma2_(unsigned long long a,
                                                    unsigned long long b,
                                                    unsigned long long c) {
    unsigned long long d;
    asm("fma.rn.f32x2 %0, %1, %2, %3;" : "=l"(d) : "l"(a), "l"(b), "l"(c));
    return d;
}
__device__ __forceinline__ unsigned long long add2_(unsigned long long a,
                                                    unsigned long long b) {
    unsigned long long d;
    asm("add.rn.f32x2 %0, %1, %2;" : "=l"(d) : "l"(a), "l"(b));
    return d;
}

__device__ __forceinline__ float fsig(float x) {
    return __fdividef(1.0f, 1.0f + __expf(-x));
}
__device__ __forceinline__ float ftanh_(float x) {
    x = fminf(fmaxf(x, -15.0f), 15.0f);
    float e = __expf(2.0f * x);
    return __fdividef(e - 1.0f, e + 1.0f);
}

// ---------------------------------------------------------------------------
// Dummy kernel: shifts the ncu capture window (-s 5 -c 1) so that k_lstm
// lands on the profiled launch slot. Negligible runtime.
// ---------------------------------------------------------------------------
__device__ int g_dummy_sink;
__global__ void k_nop(int v) { if (threadIdx.x == 1025) g_dummy_sink = v; }

// ---------------------------------------------------------------------------
// K1: fused embedding-gather + input GEMM (A duplicated in smem, u64 B pairs).
// ---------------------------------------------------------------------------
__global__ void __launch_bounds__(256, 2)
k_ingemm(const int* __restrict__ text, const float* __restrict__ emb,
         const float* __restrict__ Wf, const float* __restrict__ bf,
         const float* __restrict__ Wb, const float* __restrict__ bb)
{
    extern __shared__ char sm1raw[];
    unsigned long long* As2 = (unsigned long long*)sm1raw;   // 64 x 130 u64
    float* Bs = (float*)(As2 + 64 * 130);                    // 128 x 64 f32
    int*   toks = (int*)(Bs + 128 * 64);                     // 64

    int bx = blockIdx.x, by = blockIdx.y, tid = threadIdx.x;
    const float* W; const float* bias; float* out; int ncol0;
    if (by < 16) { W = Wf; bias = bf; out = g_xzf; ncol0 = by * 64; }
    else         { W = Wb; bias = bb; out = g_xzb; ncol0 = (by - 16) * 64; }

    if (tid < 64) toks[tid] = text[bx * 64 + tid];
    __syncthreads();

    for (int i = tid; i < 2048; i += 256) {
        int m = i >> 5, k4 = i & 31;
        float4 v = __ldg((const float4*)(emb + (size_t)toks[m] * 128) + k4);
        ulonglong2 d0, d1;
        d0.x = pk2(v.x, v.x); d0.y = pk2(v.y, v.y);
        d1.x = pk2(v.z, v.z); d1.y = pk2(v.w, v.w);
        *(ulonglong2*)(As2 + m * 130 + k4 * 4)     = d0;
        *(ulonglong2*)(As2 + m * 130 + k4 * 4 + 2) = d1;
    }
    for (int i = tid; i < 2048; i += 256) {
        int k = i >> 4, n4 = i & 15;
        float4 v = __ldg((const float4*)(W + (size_t)k * 1024 + ncol0) + n4);
        *(float4*)(Bs + k * 64 + n4 * 4) = v;
    }
    __syncthreads();

    int tx = tid & 15, ty = tid >> 4;
    const unsigned long long* Bu = (const unsigned long long*)Bs;
    unsigned long long a01[4], a23[4];
#pragma unroll
    for (int i = 0; i < 4; i++) { a01[i] = 0ULL; a23[i] = 0ULL; }

#pragma unroll 2
    for (int kb = 0; kb < 128; kb += 4) {
        ulonglong2 ar0[4], ar1[4];
#pragma unroll
        for (int i = 0; i < 4; i++) {
            ar0[i] = *(const ulonglong2*)(As2 + (ty * 4 + i) * 130 + kb);
            ar1[i] = *(const ulonglong2*)(As2 + (ty * 4 + i) * 130 + kb + 2);
        }
#pragma unroll
        for (int kq = 0; kq < 4; kq++) {
            ulonglong2 b2 = *(const ulonglong2*)(Bu + (size_t)(kb + kq) * 32 + tx * 2);
#pragma unroll
            for (int i = 0; i < 4; i++) {
                unsigned long long ad = (kq == 0) ? ar0[i].x : (kq == 1) ? ar0[i].y
                                      : (kq == 2) ? ar1[i].x : ar1[i].y;
                a01[i] = fma2_(ad, b2.x, a01[i]);
                a23[i] = fma2_(ad, b2.y, a23[i]);
            }
        }
    }

    float4 bvv = *(const float4*)(bias + ncol0 + tx * 4);
#pragma unroll
    for (int i = 0; i < 4; i++) {
        float2 p01 = unpk2(a01[i]), p23 = unpk2(a23[i]);
        float4 o;
        o.x = p01.x + bvv.x; o.y = p01.y + bvv.y;
        o.z = p23.x + bvv.z; o.w = p23.y + bvv.w;
        *(float4*)(out + (size_t)(bx * 64 + ty * 4 + i) * 1024 + ncol0 + tx * 4) = o;
    }
}

// ---------------------------------------------------------------------------
// K2: LSTM recurrence — EXACT R3 version (best measured, 3445us total).
// Launched TWICE this round (idempotent) to measure T_lstm by subtraction.
// ---------------------------------------------------------------------------
__global__ void __cluster_dims__(8, 1, 1) __launch_bounds__(512, 1)
k_lstm(const float* __restrict__ Uf, const float* __restrict__ Ub)
{
    extern __shared__ float sm2[];
    float* Uc  = sm2;                                        // 256 x 128 = 128KB
    float* hbt = sm2 + 32768;                                // 2 x 256 x 8 = 16KB
    unsigned long long* zpu = (unsigned long long*)(hbt + 4096); // 16*512 u64 = 64KB

    int tid = threadIdx.x;
    unsigned rank;
    asm("mov.u32 %0, %%cluster_ctarank;" : "=r"(rank));
    int cl = blockIdx.x >> 3;
    int dir = cl & 1, bg = cl >> 1;
    const float* U    = dir ? Ub     : Uf;
    const float* xz   = dir ? g_xzb  : g_xzf;
    float*       hout = dir ? g_hb   : g_hf;

    int w = tid >> 5, l = tid & 31;
    int k0 = w * 16;

    // Uc[k*128 + unit*4 + g] = U[k*1024 + g*256 + rank*32 + unit]
    for (int idx = tid; idx < 32768; idx += 512) {
        int k = idx >> 7, c = idx & 127;
        int unit = c >> 2, g = c & 3;
        Uc[idx] = __ldg(U + (size_t)k * 1024 + g * 256 + rank * 32 + unit);
    }
    for (int i = tid; i < 4096; i += 512) hbt[i] = 0.0f;

    bool cons = (tid < 128);
    int bp = tid >> 5;          // consumer batch-pair 0..3
    int jj = l;                 // consumer unit 0..31
    int b0 = bg * 8 + 2 * bp, b1 = b0 + 1;
    float cst0 = 0.f, cst1 = 0.f;
    float h0new = 0.f, h1new = 0.f;
    uint32_t ra[8];
    float x[8];
    if (cons) {
        uint32_t hb_addr = (uint32_t)__cvta_generic_to_shared(hbt);
        uint32_t loff = hb_addr + (uint32_t)(((rank * 32 + jj) * 8 + 2 * bp) * 4);
#pragma unroll
        for (int dc = 0; dc < 8; dc++)
            asm volatile("mapa.shared::cluster.u32 %0, %1, %2;" : "=r"(ra[dc]) : "r"(loff), "r"(dc));
        int t0 = dir ? 511 : 0;
        const float* xp0 = xz + ((size_t)b0 * 512 + t0) * 1024 + rank * 32 + jj;
        const float* xp1 = xz + ((size_t)b1 * 512 + t0) * 1024 + rank * 32 + jj;
        x[0] = __ldg(xp0); x[1] = __ldg(xp0 + 256); x[2] = __ldg(xp0 + 512); x[3] = __ldg(xp0 + 768);
        x[4] = __ldg(xp1); x[5] = __ldg(xp1 + 256); x[6] = __ldg(xp1 + 512); x[7] = __ldg(xp1 + 768);
    }
    asm volatile("barrier.cluster.arrive.aligned;\n\tbarrier.cluster.wait.aligned;" ::: "memory");

    for (int n = 0; n < 512; n++) {
        int cur = n & 1, nxt = cur ^ 1;
        int t = dir ? (511 - n) : n;

        const float* hc = hbt + cur * 2048;
        unsigned long long acc[4][4];
#pragma unroll
        for (int p = 0; p < 4; p++)
#pragma unroll
            for (int g = 0; g < 4; g++) acc[p][g] = 0ULL;

#pragma unroll
        for (int kk = 0; kk < 16; kk++) {
            int k = k0 + kk;
            float4 uq = *(const float4*)(Uc + k * 128 + l * 4);
            unsigned long long u0 = pk2(uq.x, uq.x);
            unsigned long long u1 = pk2(uq.y, uq.y);
            unsigned long long u2 = pk2(uq.z, uq.z);
            unsigned long long u3 = pk2(uq.w, uq.w);
            ulonglong2 hA = *(const ulonglong2*)(hc + k * 8);      // pairs 0,1
            ulonglong2 hB = *(const ulonglong2*)(hc + k * 8 + 4);  // pairs 2,3
            acc[0][0] = fma2_(hA.x, u0, acc[0][0]); acc[0][1] = fma2_(hA.x, u1, acc[0][1]);
            acc[0][2] = fma2_(hA.x, u2, acc[0][2]); acc[0][3] = fma2_(hA.x, u3, acc[0][3]);
            acc[1][0] = fma2_(hA.y, u0, acc[1][0]); acc[1][1] = fma2_(hA.y, u1, acc[1][1]);
            acc[1][2] = fma2_(hA.y, u2, acc[1][2]); acc[1][3] = fma2_(hA.y, u3, acc[1][3]);
            acc[2][0] = fma2_(hB.x, u0, acc[2][0]); acc[2][1] = fma2_(hB.x, u1, acc[2][1]);
            acc[2][2] = fma2_(hB.x, u2, acc[2][2]); acc[2][3] = fma2_(hB.x, u3, acc[2][3]);
            acc[3][0] = fma2_(hB.y, u0, acc[3][0]); acc[3][1] = fma2_(hB.y, u1, acc[3][1]);
            acc[3][2] = fma2_(hB.y, u2, acc[3][2]); acc[3][3] = fma2_(hB.y, u3, acc[3][3]);
        }
        // zpu slot(w,p,jj,g) = w*512 + p*128 + jj*4 + g
#pragma unroll
        for (int p = 0; p < 4; p++) {
            ulonglong2 v0, v1;
            v0.x = acc[p][0]; v0.y = acc[p][1];
            v1.x = acc[p][2]; v1.y = acc[p][3];
            *(ulonglong2*)(zpu + w * 512 + p * 128 + l * 4)     = v0;
            *(ulonglong2*)(zpu + w * 512 + p * 128 + l * 4 + 2) = v1;
        }
        __syncthreads();

        if (cons) {
            unsigned long long s0 = 0ULL, s1 = 0ULL, s2 = 0ULL, s3 = 0ULL;
#pragma unroll
            for (int w2 = 0; w2 < 16; w2++) {
                const unsigned long long* pz = zpu + w2 * 512 + bp * 128 + jj * 4;
                ulonglong2 a = *(const ulonglong2*)pz;
                ulonglong2 b = *(const ulonglong2*)(pz + 2);
                s0 = add2_(s0, a.x); s1 = add2_(s1, a.y);
                s2 = add2_(s2, b.x); s3 = add2_(s3, b.y);
            }
            float2 zi = unpk2(s0), zf = unpk2(s1), zg = unpk2(s2), zo = unpk2(s3);
            float i0 = fsig(zi.x + x[0]), f0 = fsig(zf.x + x[1]);
            float g0 = ftanh_(zg.x + x[2]), o0 = fsig(zo.x + x[3]);
            float i1 = fsig(zi.y + x[4]), f1 = fsig(zf.y + x[5]);
            float g1 = ftanh_(zg.y + x[6]), o1 = fsig(zo.y + x[7]);
            cst0 = f0 * cst0 + i0 * g0;
            cst1 = f1 * cst1 + i1 * g1;
            h0new = o0 * ftanh_(cst0);
            h1new = o1 * ftanh_(cst1);

            uint32_t poff = (uint32_t)(nxt * 2048 * 4);
#pragma unroll
            for (int dc = 0; dc < 8; dc++)
                asm volatile("st.shared::cluster.v2.f32 [%0], {%1, %2};"
                             :: "r"(ra[dc] + poff), "f"(h0new), "f"(h1new));
        }
        asm volatile("barrier.cluster.arrive.aligned;" ::: "memory");

        // barrier shadow: global h stores + next-step xz prefetch
        if (cons) {
            hout[((size_t)b0 * 512 + t) * 256 + rank * 32 + jj] = h0new;
            hout[((size_t)b1 * 512 + t) * 256 + rank * 32 + jj] = h1new;
            if (n + 1 < 512) {
                int tn = dir ? (511 - (n + 1)) : (n + 1);
                const float* xp0 = xz + ((size_t)b0 * 512 + tn) * 1024 + rank * 32 + jj;
                const float* xp1 = xz + ((size_t)b1 * 512 + tn) * 1024 + rank * 32 + jj;
                x[0] = __ldg(xp0); x[1] = __ldg(xp0 + 256);
                x[2] = __ldg(xp0 + 512); x[3] = __ldg(xp0 + 768);
                x[4] = __ldg(xp1); x[5] = __ldg(xp1 + 256);
                x[6] = __ldg(xp1 + 512); x[7] = __ldg(xp1 + 768);
            }
        }
        asm volatile("barrier.cluster.wait.aligned;" ::: "memory");
    }
}

// ---------------------------------------------------------------------------
// K3: logits = [h_fwd ; h_bwd] @ W_d + b_d.  Warp per row, W_d^T in smem.
// ---------------------------------------------------------------------------
__global__ void k_logits(const float* __restrict__ Wd, const float* __restrict__ bd,
                         float* __restrict__ out)
{
    __shared__ float Wds[NTAGS_ * 512];
    __shared__ float bds[NTAGS_];
    int tid = threadIdx.x;
    for (int i = tid; i < 512 * NTAGS_; i += 256) {
        int k = i / NTAGS_, c = i - k * NTAGS_;
        Wds[c * 512 + k] = Wd[i];
    }
    if (tid < NTAGS_) bds[tid] = bd[tid];
    __syncthreads();

    int wid = tid >> 5, l = tid & 31;
    int r = blockIdx.x * 8 + wid;
    const float* pf = g_hf + (size_t)r * 256 + l;
    const float* pb = g_hb + (size_t)r * 256 + l;
    float hf[8], hbv[8];
#pragma unroll
    for (int i = 0; i < 8; i++) { hf[i] = pf[32 * i]; hbv[i] = pb[32 * i]; }

    float parts[NTAGS_];
#pragma unroll
    for (int c = 0; c < NTAGS_; c++) {
        float p = 0.f;
#pragma unroll
        for (int i = 0; i < 8; i++) {
            p = fmaf(hf[i],  Wds[c * 512 + 32 * i + l], p);
            p = fmaf(hbv[i], Wds[c * 512 + 256 + 32 * i + l], p);
        }
        parts[c] = p;
    }
#pragma unroll
    for (int c = 0; c < NTAGS_; c++)
#pragma unroll
        for (int off = 16; off; off >>= 1)
            parts[c] += __shfl_xor_sync(0xffffffffu, parts[c], off);

    if (l == 0) {
#pragma unroll
        for (int c = 0; c < NTAGS_; c++)
            out[(size_t)r * NTAGS_ + c] = parts[c] + bds[c];
    }
}

// ---------------------------------------------------------------------------
// K4: lens + CRF.  One warp per batch element; fast-math exp/log.
// ---------------------------------------------------------------------------
__global__ void k_crf(const int* __restrict__ text, const int* __restrict__ labels,
                      const float* __restrict__ trans, float* __restrict__ out)
{
    int b = blockIdx.x;
    int l = threadIdx.x;
    const float* lgb = out + (size_t)b * NS_ * NTAGS_;
    const int*   lab = labels + b * NS_;

    int cnt = 0;
#pragma unroll
    for (int i = 0; i < 16; i++) cnt += (text[b * NS_ + l + 32 * i] != 0) ? 1 : 0;
#pragma unroll
    for (int off = 16; off; off >>= 1) cnt += __shfl_xor_sync(0xffffffffu, cnt, off);
    int len = cnt;
    if (l == 0) out[LENS_OFF + b] = (float)len;

    float sc = 0.f;
#pragma unroll
    for (int i = 0; i < 16; i++) {
        int s = l + 32 * i;
        if (s < len)     sc += lgb[s * NTAGS_ + lab[s]];
        if (s < len - 1) sc += trans[lab[s] * NTAGS_ + lab[s + 1]];
    }
#pragma unroll
    for (int off = 16; off; off >>= 1) sc += __shfl_xor_sync(0xffffffffu, sc, off);

    int j = l;
    float tc[NTAGS_];
#pragma unroll
    for (int i = 0; i < NTAGS_; i++) tc[i] = trans[i * NTAGS_ + ((j < NTAGS_) ? j : 0)];
    float alpha = (j < NTAGS_) ? lgb[j] : -3.0e38f;

    float lt_next = (j < NTAGS_) ? lgb[NTAGS_ + j] : 0.f;
    for (int t = 1; t < NS_; t++) {
        float lt = lt_next;
        if (t + 1 < NS_) lt_next = (j < NTAGS_) ? lgb[(t + 1) * NTAGS_ + j] : 0.f;
        float vv[NTAGS_];
#pragma unroll
        for (int i = 0; i < NTAGS_; i++) {
            float ai = __shfl_sync(0xffffffffu, alpha, i);
            vv[i] = ai + tc[i];
        }
        float m01 = fmaxf(vv[0], vv[1]), m23 = fmaxf(vv[2], vv[3]);
        float m45 = fmaxf(vv[4], vv[5]), m67 = fmaxf(vv[6], vv[7]);
        float m03 = fmaxf(m01, m23), m47 = fmaxf(m45, m67);
        float mx = fmaxf(fmaxf(m03, m47), vv[8]);
        float e0 = __expf(vv[0] - mx) + __expf(vv[1] - mx);
        float e1 = __expf(vv[2] - mx) + __expf(vv[3] - mx);
        float e2 = __expf(vv[4] - mx) + __expf(vv[5] - mx);
        float e3 = __expf(vv[6] - mx) + __expf(vv[7] - mx);
        float sume = ((e0 + e1) + (e2 + e3)) + __expf(vv[8] - mx);
        float na = mx + __logf(sume) + lt;
        if ((t < len) && (j < NTAGS_)) alpha = na;
    }

    float a = (j < NTAGS_) ? alpha : -3.0e38f;
    float mx = a;
#pragma unroll
    for (int off = 16; off; off >>= 1) mx = fmaxf(mx, __shfl_xor_sync(0xffffffffu, mx, off));
    float e = (j < NTAGS_) ? __expf(a - mx) : 0.f;
#pragma unroll
    for (int off = 16; off; off >>= 1) e += __shfl_xor_sync(0xffffffffu, e, off);
    float lse = mx + __logf(e);

    if (l == 0) out[LL_OFF + b] = sc - lse;
}

// ---------------------------------------------------------------------------
extern "C" void kernel_launch(void* const* d_in, const int* in_sizes, int n_in,
                              void* d_out, int out_size)
{
    (void)in_sizes; (void)n_in; (void)out_size;
    const int*   text   = (const int*)d_in[0];
    const int*   labels = (const int*)d_in[1];
    const float* emb    = (const float*)d_in[2];
    const float* Wf     = (const float*)d_in[3];
    const float* Uf     = (const float*)d_in[4];
    const float* bf     = (const float*)d_in[5];
    const float* Wb     = (const float*)d_in[6];
    const float* Ub     = (const float*)d_in[7];
    const float* bb     = (const float*)d_in[8];
    const float* Wd     = (const float*)d_in[9];
    const float* bd     = (const float*)d_in[10];
    const float* trans  = (const float*)d_in[11];
    float* out = (float*)d_out;

    int smem1 = 64 * 130 * 8 + 128 * 64 * 4 + 64 * 4;           // 99584 B
    cudaFuncSetAttribute(k_ingemm, cudaFuncAttributeMaxDynamicSharedMemorySize, smem1);
    int smem2 = 32768 * 4 + 4096 * 4 + 8192 * 8;                // 128K+16K+64K = 212992 B
    cudaFuncSetAttribute(k_lstm, cudaFuncAttributeMaxDynamicSharedMemorySize, smem2);

    k_ingemm<<<dim3(512, 32), 256, smem1>>>(text, emb, Wf, bf, Wb, bb);
    // two dummies keep the ncu capture slot on the FIRST k_lstm
    k_nop<<<1, 32>>>(0);
    k_nop<<<1, 32>>>(1);
    // k_lstm launched TWICE (idempotent): dur(R10) - 3445us = T_lstm exactly.
    k_lstm<<<128, 512, smem2>>>(Uf, Ub);
    k_lstm<<<128, 512, smem2>>>(Uf, Ub);
    k_logits<<<4096, 256>>>(Wd, bd, out);
    k_crf<<<NB_, 32>>>(text, labels, trans, out);
}

// round 11
// speedup vs baseline: 2.9681x; 2.9681x over previous
#include <cuda_runtime.h>
#include <cstdint>
#include <math.h>

#define NB_ 64
#define NS_ 512
#define NHID_ 256
#define NTAGS_ 9
#define LOGITS_N (NB_ * NS_ * NTAGS_)   // 294912
#define LENS_OFF LOGITS_N               // 294912
#define LL_OFF   (LOGITS_N + NB_)       // 294976

// Scratch (device globals: no allocation allowed)
__device__ float g_xzf[NB_ * NS_ * 1024];   // x @ W_f + b_f
__device__ float g_xzb[NB_ * NS_ * 1024];   // x @ W_b + b_b
__device__ float g_hf[NB_ * NS_ * NHID_];
__device__ float g_hb[NB_ * NS_ * NHID_];

// ---------------- packed f32x2 helpers (sm_103a FFMA2 path) ----------------
__device__ __forceinline__ unsigned long long pk2(float lo, float hi) {
    unsigned long long r;
    asm("mov.b64 %0, {%1, %2};" : "=l"(r) : "f"(lo), "f"(hi));
    return r;
}
__device__ __forceinline__ float2 unpk2(unsigned long long v) {
    float2 r;
    asm("mov.b64 {%0, %1}, %2;" : "=f"(r.x), "=f"(r.y) : "l"(v));
    return r;
}
__device__ __forceinline__ unsigned long long fma2_(unsigned long long a,
                                                    unsigned long long b,
                                                    unsigned long long c) {
    unsigned long long d;
    asm("fma.rn.f32x2 %0, %1, %2, %3;" : "=l"(d) : "l"(a), "l"(b), "l"(c));
    return d;
}
__device__ __forceinline__ unsigned long long add2_(unsigned long long a,
                                                    unsigned long long b) {
    unsigned long long d;
    asm("add.rn.f32x2 %0, %1, %2;" : "=l"(d) : "l"(a), "l"(b));
    return d;
}

__device__ __forceinline__ float fsig(float x) {
    return __fdividef(1.0f, 1.0f + __expf(-x));
}
__device__ __forceinline__ float ftanh_(float x) {
    x = fminf(fmaxf(x, -15.0f), 15.0f);
    float e = __expf(2.0f * x);
    return __fdividef(e - 1.0f, e + 1.0f);
}

#define MBAR_INIT(addr, cnt) \
    asm volatile("mbarrier.init.shared.b64 [%0], %1;" :: "r"(addr), "r"(cnt) : "memory")
#define MBAR_ARRIVE_EXPECT_TX(addr, tx) \
    asm volatile("mbarrier.arrive.expect_tx.shared.b64 _, [%0], %1;" :: "r"(addr), "r"(tx) : "memory")
#define MBAR_WAIT_PARITY(addr, par) do {                                          \
    uint32_t _mb = (addr); uint32_t _p = (par); uint32_t _done;                   \
    asm volatile("{\n\t.reg .pred p;\n\t"                                         \
        "mbarrier.try_wait.parity.acquire.cta.shared::cta.b64 p, [%1], %2;\n\t"   \
        "selp.b32 %0, 1, 0, p;\n\t}"                                              \
        : "=r"(_done) : "r"(_mb), "r"(_p) : "memory");                            \
    if (!_done) {                                                                 \
        asm volatile("{\n\t.reg .pred P1;\n\t"                                    \
        "WL_%=:\n\t"                                                              \
        "mbarrier.try_wait.parity.acquire.cta.shared::cta.b64 P1, [%0], %1, 0x989680;\n\t" \
        "@P1 bra.uni WD_%=;\n\t"                                                  \
        "bra.uni WL_%=;\n\t"                                                      \
        "WD_%=:\n\t}" :: "r"(_mb), "r"(_p) : "memory");                           \
    }                                                                             \
} while (0)

// ---------------------------------------------------------------------------
// Dummy kernel: keeps the ncu capture slot (-s 5 -c 1) on k_lstm.
// ---------------------------------------------------------------------------
__device__ int g_dummy_sink;
__global__ void k_nop(int v) { if (threadIdx.x == 1025) g_dummy_sink = v; }

// ---------------------------------------------------------------------------
// K1: fused embedding-gather + input GEMM (A duplicated in smem, u64 B pairs).
// ---------------------------------------------------------------------------
__global__ void __launch_bounds__(256, 2)
k_ingemm(const int* __restrict__ text, const float* __restrict__ emb,
         const float* __restrict__ Wf, const float* __restrict__ bf,
         const float* __restrict__ Wb, const float* __restrict__ bb)
{
    extern __shared__ char sm1raw[];
    unsigned long long* As2 = (unsigned long long*)sm1raw;   // 64 x 130 u64
    float* Bs = (float*)(As2 + 64 * 130);                    // 128 x 64 f32
    int*   toks = (int*)(Bs + 128 * 64);                     // 64

    int bx = blockIdx.x, by = blockIdx.y, tid = threadIdx.x;
    const float* W; const float* bias; float* out; int ncol0;
    if (by < 16) { W = Wf; bias = bf; out = g_xzf; ncol0 = by * 64; }
    else         { W = Wb; bias = bb; out = g_xzb; ncol0 = (by - 16) * 64; }

    if (tid < 64) toks[tid] = text[bx * 64 + tid];
    __syncthreads();

    for (int i = tid; i < 2048; i += 256) {
        int m = i >> 5, k4 = i & 31;
        float4 v = __ldg((const float4*)(emb + (size_t)toks[m] * 128) + k4);
        ulonglong2 d0, d1;
        d0.x = pk2(v.x, v.x); d0.y = pk2(v.y, v.y);
        d1.x = pk2(v.z, v.z); d1.y = pk2(v.w, v.w);
        *(ulonglong2*)(As2 + m * 130 + k4 * 4)     = d0;
        *(ulonglong2*)(As2 + m * 130 + k4 * 4 + 2) = d1;
    }
    for (int i = tid; i < 2048; i += 256) {
        int k = i >> 4, n4 = i & 15;
        float4 v = __ldg((const float4*)(W + (size_t)k * 1024 + ncol0) + n4);
        *(float4*)(Bs + k * 64 + n4 * 4) = v;
    }
    __syncthreads();

    int tx = tid & 15, ty = tid >> 4;
    const unsigned long long* Bu = (const unsigned long long*)Bs;
    unsigned long long a01[4], a23[4];
#pragma unroll
    for (int i = 0; i < 4; i++) { a01[i] = 0ULL; a23[i] = 0ULL; }

#pragma unroll 2
    for (int kb = 0; kb < 128; kb += 4) {
        ulonglong2 ar0[4], ar1[4];
#pragma unroll
        for (int i = 0; i < 4; i++) {
            ar0[i] = *(const ulonglong2*)(As2 + (ty * 4 + i) * 130 + kb);
            ar1[i] = *(const ulonglong2*)(As2 + (ty * 4 + i) * 130 + kb + 2);
        }
#pragma unroll
        for (int kq = 0; kq < 4; kq++) {
            ulonglong2 b2 = *(const ulonglong2*)(Bu + (size_t)(kb + kq) * 32 + tx * 2);
#pragma unroll
            for (int i = 0; i < 4; i++) {
                unsigned long long ad = (kq == 0) ? ar0[i].x : (kq == 1) ? ar0[i].y
                                      : (kq == 2) ? ar1[i].x : ar1[i].y;
                a01[i] = fma2_(ad, b2.x, a01[i]);
                a23[i] = fma2_(ad, b2.y, a23[i]);
            }
        }
    }

    float4 bvv = *(const float4*)(bias + ncol0 + tx * 4);
#pragma unroll
    for (int i = 0; i < 4; i++) {
        float2 p01 = unpk2(a01[i]), p23 = unpk2(a23[i]);
        float4 o;
        o.x = p01.x + bvv.x; o.y = p01.y + bvv.y;
        o.z = p23.x + bvv.z; o.w = p23.y + bvv.w;
        *(float4*)(out + (size_t)(bx * 64 + ty * 4 + i) * 1024 + ncol0 + tx * 4) = o;
    }
}

// ---------------------------------------------------------------------------
// K2: LSTM recurrence. 8 clusters x 8 CTAs; each cluster: one direction,
// SIXTEEN batch rows (two groups A=rows[0..8), B=rows[8..16) of the super-
// group). Per step both groups advance: warps 0-7 GEMM A (K-slice 32),
// warps 8-15 GEMM B; consumers A = warps 0-3, B = warps 4-7. Each group has
// its own hbu/zpu/stg/mbarriers and R8's cp.async.bulk + expect_tx exchange.
// The per-group mbarrier wait also gates zpu reuse across iterations
// (own bulk is issued only after consumers finished reading zpu).
// ---------------------------------------------------------------------------
__global__ void __cluster_dims__(8, 1, 1) __launch_bounds__(512, 1)
k_lstm(const float* __restrict__ Uf, const float* __restrict__ Ub)
{
    extern __shared__ float sm2[];
    float* Uc = sm2;                                               // 131072 B
    unsigned long long* hbuA = (unsigned long long*)(sm2 + 32768); // 2048 u64
    unsigned long long* hbuB = hbuA + 2048;                        // 2048 u64
    ulonglong2* zpuA = (ulonglong2*)(hbuB + 2048);                 // 2048 ul2
    ulonglong2* zpuB = zpuA + 2048;                                // 2048 ul2
    unsigned long long* stgA = (unsigned long long*)(zpuB + 2048); // 128 u64
    unsigned long long* stgB = stgA + 128;                         // 128 u64
    uint32_t stgA_addr = (uint32_t)__cvta_generic_to_shared(stgA);
    uint32_t stgB_addr = (uint32_t)__cvta_generic_to_shared(stgB);
    uint32_t mbarA = stgB_addr + 128 * 8;        // mbarA[2] then mbarB[2]
    uint32_t mbarB = mbarA + 16;
    uint32_t hbuA_addr = (uint32_t)__cvta_generic_to_shared(hbuA);
    uint32_t hbuB_addr = (uint32_t)__cvta_generic_to_shared(hbuB);

    int tid = threadIdx.x;
    unsigned rank;
    asm("mov.u32 %0, %%cluster_ctarank;" : "=r"(rank));
    int cl = blockIdx.x >> 3;            // 0..7
    int dir = cl & 1, sg = cl >> 1;      // supergroup 0..3 (16 batch rows)
    const float* U    = dir ? Ub     : Uf;
    const float* xz   = dir ? g_xzb  : g_xzf;
    float*       hout = dir ? g_hb   : g_hf;

    int w = tid >> 5, l = tid & 31;
    int grp = (w >= 8);                  // GEMM group: 0=A (warps 0-7), 1=B
    int w8 = w & 7;                      // warp index within GEMM group
    int k0 = w8 * 32;

    // Uc[k*128 + unit*4 + g] = U[k*1024 + g*256 + rank*32 + unit]
    for (int idx = tid; idx < 32768; idx += 512) {
        int k = idx >> 7, c = idx & 127;
        int unit = c >> 2, g = c & 3;
        Uc[idx] = __ldg(U + (size_t)k * 1024 + g * 256 + rank * 32 + unit);
    }
    for (int i = tid; i < 4096; i += 512) hbuA[i] = 0ULL;   // covers A and B
    if (tid == 0) {
        MBAR_INIT(mbarA, 1);  MBAR_INIT(mbarA + 8, 1);
        MBAR_INIT(mbarB, 1);  MBAR_INIT(mbarB + 8, 1);
    }

    // Consumer roles: warps 0-3 -> group A pair bp=w; warps 4-7 -> group B
    bool consA = (w < 4), consB = (w >= 4 && w < 8);
    int bp = w & 3, jj = l;
    int base_b = sg * 16 + (consB ? 8 : 0);
    int b0 = base_b + 2 * bp, b1 = b0 + 1;     // valid for consA/consB only
    float cst0 = 0.f, cst1 = 0.f;
    float x[8];

    // bulk issuers: group A = warp 0 lanes 0-7; group B = warp 4 lanes 0-7
    uint32_t rdst = 0, rmbar = 0, stg_src = 0;
    bool issuer = ((w == 0 || w == 4) && l < 8);
    if (issuer) {
        uint32_t hb_a = (w == 0) ? hbuA_addr : hbuB_addr;
        uint32_t mb_a = (w == 0) ? mbarA : mbarB;
        stg_src = (w == 0) ? stgA_addr : stgB_addr;
        asm volatile("mapa.shared::cluster.u32 %0, %1, %2;" : "=r"(rdst)  : "r"(hb_a), "r"(l));
        asm volatile("mapa.shared::cluster.u32 %0, %1, %2;" : "=r"(rmbar) : "r"(mb_a), "r"(l));
    }
    asm volatile("barrier.cluster.arrive.aligned;\n\tbarrier.cluster.wait.aligned;" ::: "memory");

    uint32_t my_mbar = grp ? mbarB : mbarA;
    const unsigned long long* my_hbu = grp ? hbuB : hbuA;
    ulonglong2* my_zpu = grp ? zpuB : zpuA;

    int ph0 = 0, ph1 = 0;
    for (int n = 0; n < 512; n++) {
        int cur = n & 1, nxt = cur ^ 1;
        int t = dir ? (511 - n) : n;

        // gate on this group's h buffer for this step
        if (n) {
            uint32_t mb = my_mbar + cur * 8;
            if (cur) { MBAR_WAIT_PARITY(mb, ph1); ph1 ^= 1; }
            else     { MBAR_WAIT_PARITY(mb, ph0); ph0 ^= 1; }
        }
        if (n < 511) {
            if (tid == 0)   MBAR_ARRIVE_EXPECT_TX(mbarA + nxt * 8, 8192u);
            if (tid == 256) MBAR_ARRIVE_EXPECT_TX(mbarB + nxt * 8, 8192u);
        }

        // consumers: this step's xz (lands during GEMM)
        if (consA || consB) {
            const float* xp0 = xz + ((size_t)b0 * 512 + t) * 1024 + rank * 32 + jj;
            const float* xp1 = xz + ((size_t)b1 * 512 + t) * 1024 + rank * 32 + jj;
            x[0] = __ldg(xp0); x[1] = __ldg(xp0 + 256);
            x[2] = __ldg(xp0 + 512); x[3] = __ldg(xp0 + 768);
            x[4] = __ldg(xp1); x[5] = __ldg(xp1 + 256);
            x[6] = __ldg(xp1 + 512); x[7] = __ldg(xp1 + 768);
        }

        // GEMM: my group's z partials, K-slice 32, 4 batch-pairs
        const unsigned long long* hb = my_hbu + cur * 1024;
        unsigned long long acc[4][4];
#pragma unroll
        for (int p = 0; p < 4; p++)
#pragma unroll
            for (int g = 0; g < 4; g++) acc[p][g] = 0ULL;

#pragma unroll
        for (int kk = 0; kk < 32; kk += 2) {
            int k = k0 + kk;
            float4 uq0 = *(const float4*)(Uc + k * 128 + l * 4);
            float4 uq1 = *(const float4*)(Uc + (k + 1) * 128 + l * 4);
            unsigned long long u00 = pk2(uq0.x, uq0.x), u01 = pk2(uq0.y, uq0.y);
            unsigned long long u02 = pk2(uq0.z, uq0.z), u03 = pk2(uq0.w, uq0.w);
            unsigned long long u10 = pk2(uq1.x, uq1.x), u11 = pk2(uq1.y, uq1.y);
            unsigned long long u12 = pk2(uq1.z, uq1.z), u13 = pk2(uq1.w, uq1.w);
#pragma unroll
            for (int p = 0; p < 4; p++) {
                ulonglong2 hp = *(const ulonglong2*)(hb + p * 256 + k);  // k, k+1
                acc[p][0] = fma2_(hp.x, u00, acc[p][0]);
                acc[p][1] = fma2_(hp.x, u01, acc[p][1]);
                acc[p][2] = fma2_(hp.x, u02, acc[p][2]);
                acc[p][3] = fma2_(hp.x, u03, acc[p][3]);
                acc[p][0] = fma2_(hp.y, u10, acc[p][0]);
                acc[p][1] = fma2_(hp.y, u11, acc[p][1]);
                acc[p][2] = fma2_(hp.y, u12, acc[p][2]);
                acc[p][3] = fma2_(hp.y, u13, acc[p][3]);
            }
        }
        // zpu[w8][p][half][lane] (ul2): lane stride 16B, CF
#pragma unroll
        for (int p = 0; p < 4; p++) {
            ulonglong2 v0, v1;
            v0.x = acc[p][0]; v0.y = acc[p][1];
            v1.x = acc[p][2]; v1.y = acc[p][3];
            my_zpu[((w8 * 4 + p) * 2 + 0) * 32 + l] = v0;
            my_zpu[((w8 * 4 + p) * 2 + 1) * 32 + l] = v1;
        }
        __syncthreads();

        if (consA || consB) {
            ulonglong2* rz = consA ? zpuA : zpuB;
            unsigned long long s0 = 0ULL, s1 = 0ULL, s2 = 0ULL, s3 = 0ULL;
#pragma unroll
            for (int w2 = 0; w2 < 8; w2++) {
                ulonglong2 a = rz[((w2 * 4 + bp) * 2 + 0) * 32 + jj];
                ulonglong2 b = rz[((w2 * 4 + bp) * 2 + 1) * 32 + jj];
                s0 = add2_(s0, a.x); s1 = add2_(s1, a.y);
                s2 = add2_(s2, b.x); s3 = add2_(s3, b.y);
            }
            float2 zi = unpk2(s0), zf = unpk2(s1), zg = unpk2(s2), zo = unpk2(s3);
            float i0 = fsig(zi.x + x[0]), f0 = fsig(zf.x + x[1]);
            float g0 = ftanh_(zg.x + x[2]), o0 = fsig(zo.x + x[3]);
            float i1 = fsig(zi.y + x[4]), f1 = fsig(zf.y + x[5]);
            float g1 = ftanh_(zg.y + x[6]), o1 = fsig(zo.y + x[7]);
            cst0 = f0 * cst0 + i0 * g0;
            cst1 = f1 * cst1 + i1 * g1;
            float h0new = o0 * ftanh_(cst0);
            float h1new = o1 * ftanh_(cst1);
            unsigned long long* st = consA ? stgA : stgB;
            st[bp * 32 + jj] = pk2(h0new, h1new);   // lane-stride 8B, CF

            // group-local barrier: A = warps 0-3 (id 1), B = warps 4-7 (id 2)
            if (consA) asm volatile("bar.sync 1, 128;" ::: "memory");
            else       asm volatile("bar.sync 2, 128;" ::: "memory");

            if (issuer && n < 511) {
                asm volatile("fence.proxy.async.shared::cta;" ::: "memory");
#pragma unroll
                for (int p = 0; p < 4; p++) {
                    uint32_t dst = rdst + (uint32_t)(((nxt * 4 + p) * 256 + rank * 32) * 8);
                    uint32_t src = stg_src + (uint32_t)(p * 256);
                    asm volatile(
                        "cp.async.bulk.shared::cluster.shared::cta.mbarrier::complete_tx::bytes "
                        "[%0], [%1], %2, [%3];"
                        :: "r"(dst), "r"(src), "r"(256u), "r"(rmbar + nxt * 8)
                        : "memory");
                }
            }
            // off the critical path: global h stores
            hout[((size_t)b0 * 512 + t) * 256 + rank * 32 + jj] = h0new;
            hout[((size_t)b1 * 512 + t) * 256 + rank * 32 + jj] = h1new;
        }
    }
}

// ---------------------------------------------------------------------------
// K3: logits = [h_fwd ; h_bwd] @ W_d + b_d.  Warp per row, W_d^T in smem.
// ---------------------------------------------------------------------------
__global__ void k_logits(const float* __restrict__ Wd, const float* __restrict__ bd,
                         float* __restrict__ out)
{
    __shared__ float Wds[NTAGS_ * 512];
    __shared__ float bds[NTAGS_];
    int tid = threadIdx.x;
    for (int i = tid; i < 512 * NTAGS_; i += 256) {
        int k = i / NTAGS_, c = i - k * NTAGS_;
        Wds[c * 512 + k] = Wd[i];
    }
    if (tid < NTAGS_) bds[tid] = bd[tid];
    __syncthreads();

    int wid = tid >> 5, l = tid & 31;
    int r = blockIdx.x * 8 + wid;
    const float* pf = g_hf + (size_t)r * 256 + l;
    const float* pb = g_hb + (size_t)r * 256 + l;
    float hf[8], hbv[8];
#pragma unroll
    for (int i = 0; i < 8; i++) { hf[i] = pf[32 * i]; hbv[i] = pb[32 * i]; }

    float parts[NTAGS_];
#pragma unroll
    for (int c = 0; c < NTAGS_; c++) {
        float p = 0.f;
#pragma unroll
        for (int i = 0; i < 8; i++) {
            p = fmaf(hf[i],  Wds[c * 512 + 32 * i + l], p);
            p = fmaf(hbv[i], Wds[c * 512 + 256 + 32 * i + l], p);
        }
        parts[c] = p;
    }
#pragma unroll
    for (int c = 0; c < NTAGS_; c++)
#pragma unroll
        for (int off = 16; off; off >>= 1)
            parts[c] += __shfl_xor_sync(0xffffffffu, parts[c], off);

    if (l == 0) {
#pragma unroll
        for (int c = 0; c < NTAGS_; c++)
            out[(size_t)r * NTAGS_ + c] = parts[c] + bds[c];
    }
}

// ---------------------------------------------------------------------------
// K4: lens + CRF.  One warp per batch element; fast-math exp/log.
// ---------------------------------------------------------------------------
__global__ void k_crf(const int* __restrict__ text, const int* __restrict__ labels,
                      const float* __restrict__ trans, float* __restrict__ out)
{
    int b = blockIdx.x;
    int l = threadIdx.x;
    const float* lgb = out + (size_t)b * NS_ * NTAGS_;
    const int*   lab = labels + b * NS_;

    int cnt = 0;
#pragma unroll
    for (int i = 0; i < 16; i++) cnt += (text[b * NS_ + l + 32 * i] != 0) ? 1 : 0;
#pragma unroll
    for (int off = 16; off; off >>= 1) cnt += __shfl_xor_sync(0xffffffffu, cnt, off);
    int len = cnt;
    if (l == 0) out[LENS_OFF + b] = (float)len;

    float sc = 0.f;
#pragma unroll
    for (int i = 0; i < 16; i++) {
        int s = l + 32 * i;
        if (s < len)     sc += lgb[s * NTAGS_ + lab[s]];
        if (s < len - 1) sc += trans[lab[s] * NTAGS_ + lab[s + 1]];
    }
#pragma unroll
    for (int off = 16; off; off >>= 1) sc += __shfl_xor_sync(0xffffffffu, sc, off);

    int j = l;
    float tc[NTAGS_];
#pragma unroll
    for (int i = 0; i < NTAGS_; i++) tc[i] = trans[i * NTAGS_ + ((j < NTAGS_) ? j : 0)];
    float alpha = (j < NTAGS_) ? lgb[j] : -3.0e38f;

    float lt_next = (j < NTAGS_) ? lgb[NTAGS_ + j] : 0.f;
    for (int t = 1; t < NS_; t++) {
        float lt = lt_next;
        if (t + 1 < NS_) lt_next = (j < NTAGS_) ? lgb[(t + 1) * NTAGS_ + j] : 0.f;
        float vv[NTAGS_];
#pragma unroll
        for (int i = 0; i < NTAGS_; i++) {
            float ai = __shfl_sync(0xffffffffu, alpha, i);
            vv[i] = ai + tc[i];
        }
        float m01 = fmaxf(vv[0], vv[1]), m23 = fmaxf(vv[2], vv[3]);
        float m45 = fmaxf(vv[4], vv[5]), m67 = fmaxf(vv[6], vv[7]);
        float m03 = fmaxf(m01, m23), m47 = fmaxf(m45, m67);
        float mx = fmaxf(fmaxf(m03, m47), vv[8]);
        float e0 = __expf(vv[0] - mx) + __expf(vv[1] - mx);
        float e1 = __expf(vv[2] - mx) + __expf(vv[3] - mx);
        float e2 = __expf(vv[4] - mx) + __expf(vv[5] - mx);
        float e3 = __expf(vv[6] - mx) + __expf(vv[7] - mx);
        float sume = ((e0 + e1) + (e2 + e3)) + __expf(vv[8] - mx);
        float na = mx + __logf(sume) + lt;
        if ((t < len) && (j < NTAGS_)) alpha = na;
    }

    float a = (j < NTAGS_) ? alpha : -3.0e38f;
    float mx = a;
#pragma unroll
    for (int off = 16; off; off >>= 1) mx = fmaxf(mx, __shfl_xor_sync(0xffffffffu, mx, off));
    float e = (j < NTAGS_) ? __expf(a - mx) : 0.f;
#pragma unroll
    for (int off = 16; off; off >>= 1) e += __shfl_xor_sync(0xffffffffu, e, off);
    float lse = mx + __logf(e);

    if (l == 0) out[LL_OFF + b] = sc - lse;
}

// ---------------------------------------------------------------------------
extern "C" void kernel_launch(void* const* d_in, const int* in_sizes, int n_in,
                              void* d_out, int out_size)
{
    (void)in_sizes; (void)n_in; (void)out_size;
    const int*   text   = (const int*)d_in[0];
    const int*   labels = (const int*)d_in[1];
    const float* emb    = (const float*)d_in[2];
    const float* Wf     = (const float*)d_in[3];
    const float* Uf     = (const float*)d_in[4];
    const float* bf     = (const float*)d_in[5];
    const float* Wb     = (const float*)d_in[6];
    const float* Ub     = (const float*)d_in[7];
    const float* bb     = (const float*)d_in[8];
    const float* Wd     = (const float*)d_in[9];
    const float* bd     = (const float*)d_in[10];
    const float* trans  = (const float*)d_in[11];
    float* out = (float*)d_out;

    int smem1 = 64 * 130 * 8 + 128 * 64 * 4 + 64 * 4;               // 99584 B
    cudaFuncSetAttribute(k_ingemm, cudaFuncAttributeMaxDynamicSharedMemorySize, smem1);
    // Uc 131072 + hbu 32768 + zpu 65536 + stg 2048 + mbar 32 = 231456 B
    int smem2 = 131072 + 32768 + 65536 + 2048 + 32;
    cudaFuncSetAttribute(k_lstm, cudaFuncAttributeMaxDynamicSharedMemorySize, smem2);

    k_ingemm<<<dim3(512, 32), 256, smem1>>>(text, emb, Wf, bf, Wb, bb);
    // dummies keep the ncu capture slot (-s 5 -c 1) on k_lstm
    k_nop<<<1, 32>>>(0);
    k_nop<<<1, 32>>>(1);
    k_lstm<<<64, 512, smem2>>>(Uf, Ub);
    k_logits<<<4096, 256>>>(Wd, bd, out);
    k_crf<<<NB_, 32>>>(text, labels, trans, out);
}

// round 12
// speedup vs baseline: 2.9968x; 1.0097x over previous
#include <cuda_runtime.h>
#include <cstdint>
#include <math.h>

#define NB_ 64
#define NS_ 512
#define NHID_ 256
#define NTAGS_ 9
#define LOGITS_N (NB_ * NS_ * NTAGS_)   // 294912
#define LENS_OFF LOGITS_N               // 294912
#define LL_OFF   (LOGITS_N + NB_)       // 294976

// Scratch (device globals: no allocation allowed)
__device__ float g_xzf[NB_ * NS_ * 1024];   // x @ W_f + b_f
__device__ float g_xzb[NB_ * NS_ * 1024];   // x @ W_b + b_b
__device__ float g_hf[NB_ * NS_ * NHID_];
__device__ float g_hb[NB_ * NS_ * NHID_];

// ---------------- packed f32x2 helpers (sm_103a FFMA2 path) ----------------
__device__ __forceinline__ unsigned long long pk2(float lo, float hi) {
    unsigned long long r;
    asm("mov.b64 %0, {%1, %2};" : "=l"(r) : "f"(lo), "f"(hi));
    return r;
}
__device__ __forceinline__ float2 unpk2(unsigned long long v) {
    float2 r;
    asm("mov.b64 {%0, %1}, %2;" : "=f"(r.x), "=f"(r.y) : "l"(v));
    return r;
}
__device__ __forceinline__ unsigned long long fma2_(unsigned long long a,
                                                    unsigned long long b,
                                                    unsigned long long c) {
    unsigned long long d;
    asm("fma.rn.f32x2 %0, %1, %2, %3;" : "=l"(d) : "l"(a), "l"(b), "l"(c));
    return d;
}
__device__ __forceinline__ unsigned long long add2_(unsigned long long a,
                                                    unsigned long long b) {
    unsigned long long d;
    asm("add.rn.f32x2 %0, %1, %2;" : "=l"(d) : "l"(a), "l"(b));
    return d;
}

__device__ __forceinline__ float fsig(float x) {
    return __fdividef(1.0f, 1.0f + __expf(-x));
}
__device__ __forceinline__ float ftanh_(float x) {
    x = fminf(fmaxf(x, -15.0f), 15.0f);
    float e = __expf(2.0f * x);
    return __fdividef(e - 1.0f, e + 1.0f);
}

#define MBAR_INIT(addr, cnt) \
    asm volatile("mbarrier.init.shared.b64 [%0], %1;" :: "r"(addr), "r"(cnt) : "memory")
#define MBAR_ARRIVE_EXPECT_TX(addr, tx) \
    asm volatile("mbarrier.arrive.expect_tx.shared.b64 _, [%0], %1;" :: "r"(addr), "r"(tx) : "memory")
#define MBAR_WAIT_PARITY(addr, par) do {                                          \
    uint32_t _mb = (addr); uint32_t _p = (par); uint32_t _done;                   \
    asm volatile("{\n\t.reg .pred p;\n\t"                                         \
        "mbarrier.try_wait.parity.acquire.cta.shared::cta.b64 p, [%1], %2;\n\t"   \
        "selp.b32 %0, 1, 0, p;\n\t}"                                              \
        : "=r"(_done) : "r"(_mb), "r"(_p) : "memory");                            \
    if (!_done) {                                                                 \
        asm volatile("{\n\t.reg .pred P1;\n\t"                                    \
        "WL_%=:\n\t"                                                              \
        "mbarrier.try_wait.parity.acquire.cta.shared::cta.b64 P1, [%0], %1, 0x989680;\n\t" \
        "@P1 bra.uni WD_%=;\n\t"                                                  \
        "bra.uni WL_%=;\n\t"                                                      \
        "WD_%=:\n\t}" :: "r"(_mb), "r"(_p) : "memory");                           \
    }                                                                             \
} while (0)

// ---------------------------------------------------------------------------
// Dummy kernel: keeps the ncu capture slot (-s 5 -c 1) on k_lstm.
// ---------------------------------------------------------------------------
__device__ int g_dummy_sink;
__global__ void k_nop(int v) { if (threadIdx.x == 1025) g_dummy_sink = v; }

// ---------------------------------------------------------------------------
// K1: fused embedding-gather + input GEMM (A duplicated in smem, u64 B pairs).
// ---------------------------------------------------------------------------
__global__ void __launch_bounds__(256, 2)
k_ingemm(const int* __restrict__ text, const float* __restrict__ emb,
         const float* __restrict__ Wf, const float* __restrict__ bf,
         const float* __restrict__ Wb, const float* __restrict__ bb)
{
    extern __shared__ char sm1raw[];
    unsigned long long* As2 = (unsigned long long*)sm1raw;   // 64 x 130 u64
    float* Bs = (float*)(As2 + 64 * 130);                    // 128 x 64 f32
    int*   toks = (int*)(Bs + 128 * 64);                     // 64

    int bx = blockIdx.x, by = blockIdx.y, tid = threadIdx.x;
    const float* W; const float* bias; float* out; int ncol0;
    if (by < 16) { W = Wf; bias = bf; out = g_xzf; ncol0 = by * 64; }
    else         { W = Wb; bias = bb; out = g_xzb; ncol0 = (by - 16) * 64; }

    if (tid < 64) toks[tid] = text[bx * 64 + tid];
    __syncthreads();

    for (int i = tid; i < 2048; i += 256) {
        int m = i >> 5, k4 = i & 31;
        float4 v = __ldg((const float4*)(emb + (size_t)toks[m] * 128) + k4);
        ulonglong2 d0, d1;
        d0.x = pk2(v.x, v.x); d0.y = pk2(v.y, v.y);
        d1.x = pk2(v.z, v.z); d1.y = pk2(v.w, v.w);
        *(ulonglong2*)(As2 + m * 130 + k4 * 4)     = d0;
        *(ulonglong2*)(As2 + m * 130 + k4 * 4 + 2) = d1;
    }
    for (int i = tid; i < 2048; i += 256) {
        int k = i >> 4, n4 = i & 15;
        float4 v = __ldg((const float4*)(W + (size_t)k * 1024 + ncol0) + n4);
        *(float4*)(Bs + k * 64 + n4 * 4) = v;
    }
    __syncthreads();

    int tx = tid & 15, ty = tid >> 4;
    const unsigned long long* Bu = (const unsigned long long*)Bs;
    unsigned long long a01[4], a23[4];
#pragma unroll
    for (int i = 0; i < 4; i++) { a01[i] = 0ULL; a23[i] = 0ULL; }

#pragma unroll 2
    for (int kb = 0; kb < 128; kb += 4) {
        ulonglong2 ar0[4], ar1[4];
#pragma unroll
        for (int i = 0; i < 4; i++) {
            ar0[i] = *(const ulonglong2*)(As2 + (ty * 4 + i) * 130 + kb);
            ar1[i] = *(const ulonglong2*)(As2 + (ty * 4 + i) * 130 + kb + 2);
        }
#pragma unroll
        for (int kq = 0; kq < 4; kq++) {
            ulonglong2 b2 = *(const ulonglong2*)(Bu + (size_t)(kb + kq) * 32 + tx * 2);
#pragma unroll
            for (int i = 0; i < 4; i++) {
                unsigned long long ad = (kq == 0) ? ar0[i].x : (kq == 1) ? ar0[i].y
                                      : (kq == 2) ? ar1[i].x : ar1[i].y;
                a01[i] = fma2_(ad, b2.x, a01[i]);
                a23[i] = fma2_(ad, b2.y, a23[i]);
            }
        }
    }

    float4 bvv = *(const float4*)(bias + ncol0 + tx * 4);
#pragma unroll
    for (int i = 0; i < 4; i++) {
        float2 p01 = unpk2(a01[i]), p23 = unpk2(a23[i]);
        float4 o;
        o.x = p01.x + bvv.x; o.y = p01.y + bvv.y;
        o.z = p23.x + bvv.z; o.w = p23.y + bvv.w;
        *(float4*)(out + (size_t)(bx * 64 + ty * 4 + i) * 1024 + ncol0 + tx * 4) = o;
    }
}

// ---------------------------------------------------------------------------
// K2: LSTM recurrence. 8 clusters x 8 CTAs; per cluster one direction and
// 16 batch rows in TWO FULLY DECOUPLED groups:
//   group A: warps 0-7  (consumers 0-3),  rows sg*16 + [0..8)
//   group B: warps 8-15 (consumers 8-11), rows sg*16 + [8..16)
// Each group has its own hbu/zpu/stg/mbarriers, its own named barriers
// (A: bar1(256)/bar3(128); B: bar2(256)/bar4(128)) and R8's cp.async.bulk
// + expect_tx exchange. NO __syncthreads in the loop -> groups free-run,
// one group's GEMM fills the other's exchange-wait shadow.
// ---------------------------------------------------------------------------
__global__ void __cluster_dims__(8, 1, 1) __launch_bounds__(512, 1)
k_lstm(const float* __restrict__ Uf, const float* __restrict__ Ub)
{
    extern __shared__ float sm2[];
    float* Uc = sm2;                                               // 131072 B
    unsigned long long* hbuA = (unsigned long long*)(sm2 + 32768); // 2048 u64
    unsigned long long* hbuB = hbuA + 2048;                        // 2048 u64
    ulonglong2* zpuA = (ulonglong2*)(hbuB + 2048);                 // 2048 ul2
    ulonglong2* zpuB = zpuA + 2048;                                // 2048 ul2
    unsigned long long* stgA = (unsigned long long*)(zpuB + 2048); // 128 u64
    unsigned long long* stgB = stgA + 128;                         // 128 u64
    uint32_t stgA_addr = (uint32_t)__cvta_generic_to_shared(stgA);
    uint32_t stgB_addr = (uint32_t)__cvta_generic_to_shared(stgB);
    uint32_t mbarA = stgB_addr + 128 * 8;        // mbarA[2] then mbarB[2]
    uint32_t mbarB = mbarA + 16;
    uint32_t hbuA_addr = (uint32_t)__cvta_generic_to_shared(hbuA);
    uint32_t hbuB_addr = (uint32_t)__cvta_generic_to_shared(hbuB);

    int tid = threadIdx.x;
    unsigned rank;
    asm("mov.u32 %0, %%cluster_ctarank;" : "=r"(rank));
    int cl = blockIdx.x >> 3;            // 0..7
    int dir = cl & 1, sg = cl >> 1;      // supergroup 0..3 (16 batch rows)
    const float* U    = dir ? Ub     : Uf;
    const float* xz   = dir ? g_xzb  : g_xzf;
    float*       hout = dir ? g_hb   : g_hf;

    int w = tid >> 5, l = tid & 31;
    int grp = (w >= 8);                  // 0 = A (warps 0-7), 1 = B (8-15)
    int w8 = w & 7;                      // warp index within group
    int k0 = w8 * 32;

    // Uc[k*128 + unit*4 + g] = U[k*1024 + g*256 + rank*32 + unit]
    for (int idx = tid; idx < 32768; idx += 512) {
        int k = idx >> 7, c = idx & 127;
        int unit = c >> 2, g = c & 3;
        Uc[idx] = __ldg(U + (size_t)k * 1024 + g * 256 + rank * 32 + unit);
    }
    for (int i = tid; i < 4096; i += 512) hbuA[i] = 0ULL;   // covers A and B
    if (tid == 0) {
        MBAR_INIT(mbarA, 1);  MBAR_INIT(mbarA + 8, 1);
        MBAR_INIT(mbarB, 1);  MBAR_INIT(mbarB + 8, 1);
    }

    // Consumers: first 4 warps of each group
    bool cons = (w8 < 4);
    int bp = w8 & 3, jj = l;
    int base_b = sg * 16 + grp * 8;
    int b0 = base_b + 2 * bp, b1 = b0 + 1;     // meaningful for consumers
    float cst0 = 0.f, cst1 = 0.f;
    float x[8];

    // bulk issuers: warp 0 (A) / warp 8 (B), lanes 0-7
    uint32_t rdst = 0, rmbar = 0, stg_src = 0;
    bool issuer = (w8 == 0 && l < 8);
    if (issuer) {
        uint32_t hb_a = grp ? hbuB_addr : hbuA_addr;
        uint32_t mb_a = grp ? mbarB : mbarA;
        stg_src = grp ? stgB_addr : stgA_addr;
        asm volatile("mapa.shared::cluster.u32 %0, %1, %2;" : "=r"(rdst)  : "r"(hb_a), "r"(l));
        asm volatile("mapa.shared::cluster.u32 %0, %1, %2;" : "=r"(rmbar) : "r"(mb_a), "r"(l));
    }
    asm volatile("barrier.cluster.arrive.aligned;\n\tbarrier.cluster.wait.aligned;" ::: "memory");

    uint32_t my_mbar = grp ? mbarB : mbarA;
    const unsigned long long* my_hbu = grp ? hbuB : hbuA;
    ulonglong2* my_zpu = grp ? zpuB : zpuA;
    unsigned long long* my_stg = grp ? stgB : stgA;

    int ph0 = 0, ph1 = 0;
    for (int n = 0; n < 512; n++) {
        int cur = n & 1, nxt = cur ^ 1;
        int t = dir ? (511 - n) : n;

        // gate on this group's h buffer for this step
        if (n) {
            uint32_t mb = my_mbar + cur * 8;
            if (cur) { MBAR_WAIT_PARITY(mb, ph1); ph1 ^= 1; }
            else     { MBAR_WAIT_PARITY(mb, ph0); ph0 ^= 1; }
        }
        if (n < 511) {
            if (tid == 0)   MBAR_ARRIVE_EXPECT_TX(mbarA + nxt * 8, 8192u);
            if (tid == 256) MBAR_ARRIVE_EXPECT_TX(mbarB + nxt * 8, 8192u);
        }

        // consumers: this step's xz (lands during GEMM)
        if (cons) {
            const float* xp0 = xz + ((size_t)b0 * 512 + t) * 1024 + rank * 32 + jj;
            const float* xp1 = xz + ((size_t)b1 * 512 + t) * 1024 + rank * 32 + jj;
            x[0] = __ldg(xp0); x[1] = __ldg(xp0 + 256);
            x[2] = __ldg(xp0 + 512); x[3] = __ldg(xp0 + 768);
            x[4] = __ldg(xp1); x[5] = __ldg(xp1 + 256);
            x[6] = __ldg(xp1 + 512); x[7] = __ldg(xp1 + 768);
        }

        // GEMM: my group's z partials, K-slice 32, 4 batch-pairs
        const unsigned long long* hb = my_hbu + cur * 1024;
        unsigned long long acc[4][4];
#pragma unroll
        for (int p = 0; p < 4; p++)
#pragma unroll
            for (int g = 0; g < 4; g++) acc[p][g] = 0ULL;

#pragma unroll
        for (int kk = 0; kk < 32; kk += 2) {
            int k = k0 + kk;
            float4 uq0 = *(const float4*)(Uc + k * 128 + l * 4);
            float4 uq1 = *(const float4*)(Uc + (k + 1) * 128 + l * 4);
            unsigned long long u00 = pk2(uq0.x, uq0.x), u01 = pk2(uq0.y, uq0.y);
            unsigned long long u02 = pk2(uq0.z, uq0.z), u03 = pk2(uq0.w, uq0.w);
            unsigned long long u10 = pk2(uq1.x, uq1.x), u11 = pk2(uq1.y, uq1.y);
            unsigned long long u12 = pk2(uq1.z, uq1.z), u13 = pk2(uq1.w, uq1.w);
#pragma unroll
            for (int p = 0; p < 4; p++) {
                ulonglong2 hp = *(const ulonglong2*)(hb + p * 256 + k);  // k, k+1
                acc[p][0] = fma2_(hp.x, u00, acc[p][0]);
                acc[p][1] = fma2_(hp.x, u01, acc[p][1]);
                acc[p][2] = fma2_(hp.x, u02, acc[p][2]);
                acc[p][3] = fma2_(hp.x, u03, acc[p][3]);
                acc[p][0] = fma2_(hp.y, u10, acc[p][0]);
                acc[p][1] = fma2_(hp.y, u11, acc[p][1]);
                acc[p][2] = fma2_(hp.y, u12, acc[p][2]);
                acc[p][3] = fma2_(hp.y, u13, acc[p][3]);
            }
        }
        // zpu[w8][p][half][lane] (ul2): lane stride 16B, CF
#pragma unroll
        for (int p = 0; p < 4; p++) {
            ulonglong2 v0, v1;
            v0.x = acc[p][0]; v0.y = acc[p][1];
            v1.x = acc[p][2]; v1.y = acc[p][3];
            my_zpu[((w8 * 4 + p) * 2 + 0) * 32 + l] = v0;
            my_zpu[((w8 * 4 + p) * 2 + 1) * 32 + l] = v1;
        }
        // group barrier: zpu writes -> reads (A: id1, B: id2; 256 threads)
        if (grp) asm volatile("bar.sync 2, 256;" ::: "memory");
        else     asm volatile("bar.sync 1, 256;" ::: "memory");

        if (cons) {
            unsigned long long s0 = 0ULL, s1 = 0ULL, s2 = 0ULL, s3 = 0ULL;
#pragma unroll
            for (int w2 = 0; w2 < 8; w2++) {
                ulonglong2 a = my_zpu[((w2 * 4 + bp) * 2 + 0) * 32 + jj];
                ulonglong2 b = my_zpu[((w2 * 4 + bp) * 2 + 1) * 32 + jj];
                s0 = add2_(s0, a.x); s1 = add2_(s1, a.y);
                s2 = add2_(s2, b.x); s3 = add2_(s3, b.y);
            }
            float2 zi = unpk2(s0), zf = unpk2(s1), zg = unpk2(s2), zo = unpk2(s3);
            float i0 = fsig(zi.x + x[0]), f0 = fsig(zf.x + x[1]);
            float g0 = ftanh_(zg.x + x[2]), o0 = fsig(zo.x + x[3]);
            float i1 = fsig(zi.y + x[4]), f1 = fsig(zf.y + x[5]);
            float g1 = ftanh_(zg.y + x[6]), o1 = fsig(zo.y + x[7]);
            cst0 = f0 * cst0 + i0 * g0;
            cst1 = f1 * cst1 + i1 * g1;
            float h0new = o0 * ftanh_(cst0);
            float h1new = o1 * ftanh_(cst1);
            my_stg[bp * 32 + jj] = pk2(h0new, h1new);   // lane-stride 8B, CF

            // consumer barrier: stg/zpu-reads done before bulk issue
            if (grp) asm volatile("bar.sync 4, 128;" ::: "memory");
            else     asm volatile("bar.sync 3, 128;" ::: "memory");

            if (issuer && n < 511) {
                asm volatile("fence.proxy.async.shared::cta;" ::: "memory");
#pragma unroll
                for (int p = 0; p < 4; p++) {
                    uint32_t dst = rdst + (uint32_t)(((nxt * 4 + p) * 256 + rank * 32) * 8);
                    uint32_t src = stg_src + (uint32_t)(p * 256);
                    asm volatile(
                        "cp.async.bulk.shared::cluster.shared::cta.mbarrier::complete_tx::bytes "
                        "[%0], [%1], %2, [%3];"
                        :: "r"(dst), "r"(src), "r"(256u), "r"(rmbar + nxt * 8)
                        : "memory");
                }
            }
            // off the critical path: global h stores
            hout[((size_t)b0 * 512 + t) * 256 + rank * 32 + jj] = h0new;
            hout[((size_t)b1 * 512 + t) * 256 + rank * 32 + jj] = h1new;
        }
    }
}

// ---------------------------------------------------------------------------
// K3: logits = [h_fwd ; h_bwd] @ W_d + b_d.  Warp per row, W_d^T in smem.
// ---------------------------------------------------------------------------
__global__ void k_logits(const float* __restrict__ Wd, const float* __restrict__ bd,
                         float* __restrict__ out)
{
    __shared__ float Wds[NTAGS_ * 512];
    __shared__ float bds[NTAGS_];
    int tid = threadIdx.x;
    for (int i = tid; i < 512 * NTAGS_; i += 256) {
        int k = i / NTAGS_, c = i - k * NTAGS_;
        Wds[c * 512 + k] = Wd[i];
    }
    if (tid < NTAGS_) bds[tid] = bd[tid];
    __syncthreads();

    int wid = tid >> 5, l = tid & 31;
    int r = blockIdx.x * 8 + wid;
    const float* pf = g_hf + (size_t)r * 256 + l;
    const float* pb = g_hb + (size_t)r * 256 + l;
    float hf[8], hbv[8];
#pragma unroll
    for (int i = 0; i < 8; i++) { hf[i] = pf[32 * i]; hbv[i] = pb[32 * i]; }

    float parts[NTAGS_];
#pragma unroll
    for (int c = 0; c < NTAGS_; c++) {
        float p = 0.f;
#pragma unroll
        for (int i = 0; i < 8; i++) {
            p = fmaf(hf[i],  Wds[c * 512 + 32 * i + l], p);
            p = fmaf(hbv[i], Wds[c * 512 + 256 + 32 * i + l], p);
        }
        parts[c] = p;
    }
#pragma unroll
    for (int c = 0; c < NTAGS_; c++)
#pragma unroll
        for (int off = 16; off; off >>= 1)
            parts[c] += __shfl_xor_sync(0xffffffffu, parts[c], off);

    if (l == 0) {
#pragma unroll
        for (int c = 0; c < NTAGS_; c++)
            out[(size_t)r * NTAGS_ + c] = parts[c] + bds[c];
    }
}

// ---------------------------------------------------------------------------
// K4: lens + CRF.  One warp per batch element; fast-math exp/log.
// ---------------------------------------------------------------------------
__global__ void k_crf(const int* __restrict__ text, const int* __restrict__ labels,
                      const float* __restrict__ trans, float* __restrict__ out)
{
    int b = blockIdx.x;
    int l = threadIdx.x;
    const float* lgb = out + (size_t)b * NS_ * NTAGS_;
    const int*   lab = labels + b * NS_;

    int cnt = 0;
#pragma unroll
    for (int i = 0; i < 16; i++) cnt += (text[b * NS_ + l + 32 * i] != 0) ? 1 : 0;
#pragma unroll
    for (int off = 16; off; off >>= 1) cnt += __shfl_xor_sync(0xffffffffu, cnt, off);
    int len = cnt;
    if (l == 0) out[LENS_OFF + b] = (float)len;

    float sc = 0.f;
#pragma unroll
    for (int i = 0; i < 16; i++) {
        int s = l + 32 * i;
        if (s < len)     sc += lgb[s * NTAGS_ + lab[s]];
        if (s < len - 1) sc += trans[lab[s] * NTAGS_ + lab[s + 1]];
    }
#pragma unroll
    for (int off = 16; off; off >>= 1) sc += __shfl_xor_sync(0xffffffffu, sc, off);

    int j = l;
    float tc[NTAGS_];
#pragma unroll
    for (int i = 0; i < NTAGS_; i++) tc[i] = trans[i * NTAGS_ + ((j < NTAGS_) ? j : 0)];
    float alpha = (j < NTAGS_) ? lgb[j] : -3.0e38f;

    float lt_next = (j < NTAGS_) ? lgb[NTAGS_ + j] : 0.f;
    for (int t = 1; t < NS_; t++) {
        float lt = lt_next;
        if (t + 1 < NS_) lt_next = (j < NTAGS_) ? lgb[(t + 1) * NTAGS_ + j] : 0.f;
        float vv[NTAGS_];
#pragma unroll
        for (int i = 0; i < NTAGS_; i++) {
            float ai = __shfl_sync(0xffffffffu, alpha, i);
            vv[i] = ai + tc[i];
        }
        float m01 = fmaxf(vv[0], vv[1]), m23 = fmaxf(vv[2], vv[3]);
        float m45 = fmaxf(vv[4], vv[5]), m67 = fmaxf(vv[6], vv[7]);
        float m03 = fmaxf(m01, m23), m47 = fmaxf(m45, m67);
        float mx = fmaxf(fmaxf(m03, m47), vv[8]);
        float e0 = __expf(vv[0] - mx) + __expf(vv[1] - mx);
        float e1 = __expf(vv[2] - mx) + __expf(vv[3] - mx);
        float e2 = __expf(vv[4] - mx) + __expf(vv[5] - mx);
        float e3 = __expf(vv[6] - mx) + __expf(vv[7] - mx);
        float sume = ((e0 + e1) + (e2 + e3)) + __expf(vv[8] - mx);
        float na = mx + __logf(sume) + lt;
        if ((t < len) && (j < NTAGS_)) alpha = na;
    }

    float a = (j < NTAGS_) ? alpha : -3.0e38f;
    float mx = a;
#pragma unroll
    for (int off = 16; off; off >>= 1) mx = fmaxf(mx, __shfl_xor_sync(0xffffffffu, mx, off));
    float e = (j < NTAGS_) ? __expf(a - mx) : 0.f;
#pragma unroll
    for (int off = 16; off; off >>= 1) e += __shfl_xor_sync(0xffffffffu, e, off);
    float lse = mx + __logf(e);

    if (l == 0) out[LL_OFF + b] = sc - lse;
}

// ---------------------------------------------------------------------------
extern "C" void kernel_launch(void* const* d_in, const int* in_sizes, int n_in,
                              void* d_out, int out_size)
{
    (void)in_sizes; (void)n_in; (void)out_size;
    const int*   text   = (const int*)d_in[0];
    const int*   labels = (const int*)d_in[1];
    const float* emb    = (const float*)d_in[2];
    const float* Wf     = (const float*)d_in[3];
    const float* Uf     = (const float*)d_in[4];
    const float* bf     = (const float*)d_in[5];
    const float* Wb     = (const float*)d_in[6];
    const float* Ub     = (const float*)d_in[7];
    const float* bb     = (const float*)d_in[8];
    const float* Wd     = (const float*)d_in[9];
    const float* bd     = (const float*)d_in[10];
    const float* trans  = (const float*)d_in[11];
    float* out = (float*)d_out;

    int smem1 = 64 * 130 * 8 + 128 * 64 * 4 + 64 * 4;               // 99584 B
    cudaFuncSetAttribute(k_ingemm, cudaFuncAttributeMaxDynamicSharedMemorySize, smem1);
    // Uc 131072 + hbu 32768 + zpu 65536 + stg 2048 + mbar 32 = 231456 B
    int smem2 = 131072 + 32768 + 65536 + 2048 + 32;
    cudaFuncSetAttribute(k_lstm, cudaFuncAttributeMaxDynamicSharedMemorySize, smem2);

    k_ingemm<<<dim3(512, 32), 256, smem1>>>(text, emb, Wf, bf, Wb, bb);
    // dummies keep the ncu capture slot (-s 5 -c 1) on k_lstm
    k_nop<<<1, 32>>>(0);
    k_nop<<<1, 32>>>(1);
    k_lstm<<<64, 512, smem2>>>(Uf, Ub);
    k_logits<<<4096, 256>>>(Wd, bd, out);
    k_crf<<<NB_, 32>>>(text, labels, trans, out);
}

// round 17
// speedup vs baseline: 3.0422x; 1.0151x over previous
#include <cuda_runtime.h>
#include <cstdint>
#include <math.h>

#define NB_ 64
#define NS_ 512
#define NHID_ 256
#define NTAGS_ 9
#define LOGITS_N (NB_ * NS_ * NTAGS_)   // 294912
#define LENS_OFF LOGITS_N               // 294912
#define LL_OFF   (LOGITS_N + NB_)       // 294976

// Scratch (device globals: no allocation allowed)
__device__ float g_xzf[NB_ * NS_ * 1024];   // x @ W_f + b_f
__device__ float g_xzb[NB_ * NS_ * 1024];   // x @ W_b + b_b
__device__ float g_hf[NB_ * NS_ * NHID_];
__device__ float g_hb[NB_ * NS_ * NHID_];

// ---------------- packed f32x2 helpers (sm_103a FFMA2 path) ----------------
__device__ __forceinline__ unsigned long long pk2(float lo, float hi) {
    unsigned long long r;
    asm("mov.b64 %0, {%1, %2};" : "=l"(r) : "f"(lo), "f"(hi));
    return r;
}
__device__ __forceinline__ float2 unpk2(unsigned long long v) {
    float2 r;
    asm("mov.b64 {%0, %1}, %2;" : "=f"(r.x), "=f"(r.y) : "l"(v));
    return r;
}
__device__ __forceinline__ unsigned long long fma2_(unsigned long long a,
                                                    unsigned long long b,
                                                    unsigned long long c) {
    unsigned long long d;
    asm("fma.rn.f32x2 %0, %1, %2, %3;" : "=l"(d) : "l"(a), "l"(b), "l"(c));
    return d;
}
__device__ __forceinline__ unsigned long long add2_(unsigned long long a,
                                                    unsigned long long b) {
    unsigned long long d;
    asm("add.rn.f32x2 %0, %1, %2;" : "=l"(d) : "l"(a), "l"(b));
    return d;
}

// HW tanh (MUFU.TANH) gates — ~1e-5 class error, tolerance is 1e-3.
__device__ __forceinline__ float tanha(float x) {
    float y; asm("tanh.approx.f32 %0, %1;" : "=f"(y) : "f"(x)); return y;
}
__device__ __forceinline__ float siga(float x) {
    return fmaf(0.5f, tanha(0.5f * x), 0.5f);
}

#define MBAR_INIT(addr, cnt) \
    asm volatile("mbarrier.init.shared.b64 [%0], %1;" :: "r"(addr), "r"(cnt) : "memory")
#define MBAR_ARRIVE_EXPECT_TX(addr, tx) \
    asm volatile("mbarrier.arrive.expect_tx.shared.b64 _, [%0], %1;" :: "r"(addr), "r"(tx) : "memory")
#define MBAR_WAIT_PARITY(addr, par) do {                                          \
    uint32_t _mb = (addr); uint32_t _p = (par); uint32_t _done;                   \
    asm volatile("{\n\t.reg .pred p;\n\t"                                         \
        "mbarrier.try_wait.parity.acquire.cta.shared::cta.b64 p, [%1], %2;\n\t"   \
        "selp.b32 %0, 1, 0, p;\n\t}"                                              \
        : "=r"(_done) : "r"(_mb), "r"(_p) : "memory");                            \
    if (!_done) {                                                                 \
        asm volatile("{\n\t.reg .pred P1;\n\t"                                    \
        "WL_%=:\n\t"                                                              \
        "mbarrier.try_wait.parity.acquire.cta.shared::cta.b64 P1, [%0], %1, 0x989680;\n\t" \
        "@P1 bra.uni WD_%=;\n\t"                                                  \
        "bra.uni WL_%=;\n\t"                                                      \
        "WD_%=:\n\t}" :: "r"(_mb), "r"(_p) : "memory");                           \
    }                                                                             \
} while (0)

// ---------------------------------------------------------------------------
// Dummy kernel: keeps the ncu capture slot (-s 5 -c 1) on k_lstm.
// ---------------------------------------------------------------------------
__device__ int g_dummy_sink;
__global__ void k_nop(int v) { if (threadIdx.x == 1025) g_dummy_sink = v; }

// ---------------------------------------------------------------------------
// K1: fused embedding-gather + input GEMM (A duplicated in smem, u64 B pairs).
// ---------------------------------------------------------------------------
__global__ void __launch_bounds__(256, 2)
k_ingemm(const int* __restrict__ text, const float* __restrict__ emb,
         const float* __restrict__ Wf, const float* __restrict__ bf,
         const float* __restrict__ Wb, const float* __restrict__ bb)
{
    extern __shared__ char sm1raw[];
    unsigned long long* As2 = (unsigned long long*)sm1raw;   // 64 x 130 u64
    float* Bs = (float*)(As2 + 64 * 130);                    // 128 x 64 f32
    int*   toks = (int*)(Bs + 128 * 64);                     // 64

    int bx = blockIdx.x, by = blockIdx.y, tid = threadIdx.x;
    const float* W; const float* bias; float* out; int ncol0;
    if (by < 16) { W = Wf; bias = bf; out = g_xzf; ncol0 = by * 64; }
    else         { W = Wb; bias = bb; out = g_xzb; ncol0 = (by - 16) * 64; }

    if (tid < 64) toks[tid] = text[bx * 64 + tid];
    __syncthreads();

    for (int i = tid; i < 2048; i += 256) {
        int m = i >> 5, k4 = i & 31;
        float4 v = __ldg((const float4*)(emb + (size_t)toks[m] * 128) + k4);
        ulonglong2 d0, d1;
        d0.x = pk2(v.x, v.x); d0.y = pk2(v.y, v.y);
        d1.x = pk2(v.z, v.z); d1.y = pk2(v.w, v.w);
        *(ulonglong2*)(As2 + m * 130 + k4 * 4)     = d0;
        *(ulonglong2*)(As2 + m * 130 + k4 * 4 + 2) = d1;
    }
    for (int i = tid; i < 2048; i += 256) {
        int k = i >> 4, n4 = i & 15;
        float4 v = __ldg((const float4*)(W + (size_t)k * 1024 + ncol0) + n4);
        *(float4*)(Bs + k * 64 + n4 * 4) = v;
    }
    __syncthreads();

    int tx = tid & 15, ty = tid >> 4;
    const unsigned long long* Bu = (const unsigned long long*)Bs;
    unsigned long long a01[4], a23[4];
#pragma unroll
    for (int i = 0; i < 4; i++) { a01[i] = 0ULL; a23[i] = 0ULL; }

#pragma unroll 2
    for (int kb = 0; kb < 128; kb += 4) {
        ulonglong2 ar0[4], ar1[4];
#pragma unroll
        for (int i = 0; i < 4; i++) {
            ar0[i] = *(const ulonglong2*)(As2 + (ty * 4 + i) * 130 + kb);
            ar1[i] = *(const ulonglong2*)(As2 + (ty * 4 + i) * 130 + kb + 2);
        }
#pragma unroll
        for (int kq = 0; kq < 4; kq++) {
            ulonglong2 b2 = *(const ulonglong2*)(Bu + (size_t)(kb + kq) * 32 + tx * 2);
#pragma unroll
            for (int i = 0; i < 4; i++) {
                unsigned long long ad = (kq == 0) ? ar0[i].x : (kq == 1) ? ar0[i].y
                                      : (kq == 2) ? ar1[i].x : ar1[i].y;
                a01[i] = fma2_(ad, b2.x, a01[i]);
                a23[i] = fma2_(ad, b2.y, a23[i]);
            }
        }
    }

    float4 bvv = *(const float4*)(bias + ncol0 + tx * 4);
#pragma unroll
    for (int i = 0; i < 4; i++) {
        float2 p01 = unpk2(a01[i]), p23 = unpk2(a23[i]);
        float4 o;
        o.x = p01.x + bvv.x; o.y = p01.y + bvv.y;
        o.z = p23.x + bvv.z; o.w = p23.y + bvv.w;
        *(float4*)(out + (size_t)(bx * 64 + ty * 4 + i) * 1024 + ncol0 + tx * 4) = o;
    }
}

// ---------------------------------------------------------------------------
// K2: LSTM recurrence. 8 clusters x 8 CTAs; per cluster one direction and
// 16 batch rows in TWO FULLY DECOUPLED groups (A: warps 0-7, B: warps 8-15).
// Exactly the proven R12 structure (bulk-copy exchange); only change:
// gates use MUFU tanh.approx (siga/tanha) instead of __expf chains.
// ---------------------------------------------------------------------------
__global__ void __cluster_dims__(8, 1, 1) __launch_bounds__(512, 1)
k_lstm(const float* __restrict__ Uf, const float* __restrict__ Ub)
{
    extern __shared__ float sm2[];
    float* Uc = sm2;                                               // 131072 B
    unsigned long long* hbuA = (unsigned long long*)(sm2 + 32768); // 2048 u64
    unsigned long long* hbuB = hbuA + 2048;                        // 2048 u64
    ulonglong2* zpuA = (ulonglong2*)(hbuB + 2048);                 // 2048 ul2
    ulonglong2* zpuB = zpuA + 2048;                                // 2048 ul2
    unsigned long long* stgA = (unsigned long long*)(zpuB + 2048); // 128 u64
    unsigned long long* stgB = stgA + 128;                         // 128 u64
    uint32_t stgA_addr = (uint32_t)__cvta_generic_to_shared(stgA);
    uint32_t stgB_addr = (uint32_t)__cvta_generic_to_shared(stgB);
    uint32_t mbarA = stgB_addr + 128 * 8;        // mbarA[2] then mbarB[2]
    uint32_t mbarB = mbarA + 16;
    uint32_t hbuA_addr = (uint32_t)__cvta_generic_to_shared(hbuA);
    uint32_t hbuB_addr = (uint32_t)__cvta_generic_to_shared(hbuB);

    int tid = threadIdx.x;
    unsigned rank;
    asm("mov.u32 %0, %%cluster_ctarank;" : "=r"(rank));
    int cl = blockIdx.x >> 3;            // 0..7
    int dir = cl & 1, sg = cl >> 1;      // supergroup 0..3 (16 batch rows)
    const float* U    = dir ? Ub     : Uf;
    const float* xz   = dir ? g_xzb  : g_xzf;
    float*       hout = dir ? g_hb   : g_hf;

    int w = tid >> 5, l = tid & 31;
    int grp = (w >= 8);                  // 0 = A (warps 0-7), 1 = B (8-15)
    int w8 = w & 7;                      // warp index within group
    int k0 = w8 * 32;

    // Uc[k*128 + unit*4 + g] = U[k*1024 + g*256 + rank*32 + unit]
    for (int idx = tid; idx < 32768; idx += 512) {
        int k = idx >> 7, c = idx & 127;
        int unit = c >> 2, g = c & 3;
        Uc[idx] = __ldg(U + (size_t)k * 1024 + g * 256 + rank * 32 + unit);
    }
    for (int i = tid; i < 4096; i += 512) hbuA[i] = 0ULL;   // covers A and B
    if (tid == 0) {
        MBAR_INIT(mbarA, 1);  MBAR_INIT(mbarA + 8, 1);
        MBAR_INIT(mbarB, 1);  MBAR_INIT(mbarB + 8, 1);
    }

    // Consumers: first 4 warps of each group
    bool cons = (w8 < 4);
    int bp = w8 & 3, jj = l;
    int base_b = sg * 16 + grp * 8;
    int b0 = base_b + 2 * bp, b1 = b0 + 1;     // meaningful for consumers
    float cst0 = 0.f, cst1 = 0.f;
    float x[8];

    // bulk issuers: warp 0 (A) / warp 8 (B), lanes 0-7
    uint32_t rdst = 0, rmbar = 0, stg_src = 0;
    bool issuer = (w8 == 0 && l < 8);
    if (issuer) {
        uint32_t hb_a = grp ? hbuB_addr : hbuA_addr;
        uint32_t mb_a = grp ? mbarB : mbarA;
        stg_src = grp ? stgB_addr : stgA_addr;
        asm volatile("mapa.shared::cluster.u32 %0, %1, %2;" : "=r"(rdst)  : "r"(hb_a), "r"(l));
        asm volatile("mapa.shared::cluster.u32 %0, %1, %2;" : "=r"(rmbar) : "r"(mb_a), "r"(l));
    }
    asm volatile("barrier.cluster.arrive.aligned;\n\tbarrier.cluster.wait.aligned;" ::: "memory");

    uint32_t my_mbar = grp ? mbarB : mbarA;
    const unsigned long long* my_hbu = grp ? hbuB : hbuA;
    ulonglong2* my_zpu = grp ? zpuB : zpuA;
    unsigned long long* my_stg = grp ? stgB : stgA;

    int ph0 = 0, ph1 = 0;
    for (int n = 0; n < 512; n++) {
        int cur = n & 1, nxt = cur ^ 1;
        int t = dir ? (511 - n) : n;

        // gate on this group's h buffer for this step
        if (n) {
            uint32_t mb = my_mbar + cur * 8;
            if (cur) { MBAR_WAIT_PARITY(mb, ph1); ph1 ^= 1; }
            else     { MBAR_WAIT_PARITY(mb, ph0); ph0 ^= 1; }
        }
        if (n < 511) {
            if (tid == 0)   MBAR_ARRIVE_EXPECT_TX(mbarA + nxt * 8, 8192u);
            if (tid == 256) MBAR_ARRIVE_EXPECT_TX(mbarB + nxt * 8, 8192u);
        }

        // consumers: this step's xz (lands during GEMM)
        if (cons) {
            const float* xp0 = xz + ((size_t)b0 * 512 + t) * 1024 + rank * 32 + jj;
            const float* xp1 = xz + ((size_t)b1 * 512 + t) * 1024 + rank * 32 + jj;
            x[0] = __ldg(xp0); x[1] = __ldg(xp0 + 256);
            x[2] = __ldg(xp0 + 512); x[3] = __ldg(xp0 + 768);
            x[4] = __ldg(xp1); x[5] = __ldg(xp1 + 256);
            x[6] = __ldg(xp1 + 512); x[7] = __ldg(xp1 + 768);
        }

        // GEMM: my group's z partials, K-slice 32, 4 batch-pairs
        const unsigned long long* hb = my_hbu + cur * 1024;
        unsigned long long acc[4][4];
#pragma unroll
        for (int p = 0; p < 4; p++)
#pragma unroll
            for (int g = 0; g < 4; g++) acc[p][g] = 0ULL;

#pragma unroll
        for (int kk = 0; kk < 32; kk += 2) {
            int k = k0 + kk;
            float4 uq0 = *(const float4*)(Uc + k * 128 + l * 4);
            float4 uq1 = *(const float4*)(Uc + (k + 1) * 128 + l * 4);
            unsigned long long u00 = pk2(uq0.x, uq0.x), u01 = pk2(uq0.y, uq0.y);
            unsigned long long u02 = pk2(uq0.z, uq0.z), u03 = pk2(uq0.w, uq0.w);
            unsigned long long u10 = pk2(uq1.x, uq1.x), u11 = pk2(uq1.y, uq1.y);
            unsigned long long u12 = pk2(uq1.z, uq1.z), u13 = pk2(uq1.w, uq1.w);
#pragma unroll
            for (int p = 0; p < 4; p++) {
                ulonglong2 hp = *(const ulonglong2*)(hb + p * 256 + k);  // k, k+1
                acc[p][0] = fma2_(hp.x, u00, acc[p][0]);
                acc[p][1] = fma2_(hp.x, u01, acc[p][1]);
                acc[p][2] = fma2_(hp.x, u02, acc[p][2]);
                acc[p][3] = fma2_(hp.x, u03, acc[p][3]);
                acc[p][0] = fma2_(hp.y, u10, acc[p][0]);
                acc[p][1] = fma2_(hp.y, u11, acc[p][1]);
                acc[p][2] = fma2_(hp.y, u12, acc[p][2]);
                acc[p][3] = fma2_(hp.y, u13, acc[p][3]);
            }
        }
        // zpu[w8][p][half][lane] (ul2): lane stride 16B, CF
#pragma unroll
        for (int p = 0; p < 4; p++) {
            ulonglong2 v0, v1;
            v0.x = acc[p][0]; v0.y = acc[p][1];
            v1.x = acc[p][2]; v1.y = acc[p][3];
            my_zpu[((w8 * 4 + p) * 2 + 0) * 32 + l] = v0;
            my_zpu[((w8 * 4 + p) * 2 + 1) * 32 + l] = v1;
        }
        // group barrier: zpu writes -> reads (A: id1, B: id2; 256 threads)
        if (grp) asm volatile("bar.sync 2, 256;" ::: "memory");
        else     asm volatile("bar.sync 1, 256;" ::: "memory");

        if (cons) {
            unsigned long long s0 = 0ULL, s1 = 0ULL, s2 = 0ULL, s3 = 0ULL;
#pragma unroll
            for (int w2 = 0; w2 < 8; w2++) {
                ulonglong2 a = my_zpu[((w2 * 4 + bp) * 2 + 0) * 32 + jj];
                ulonglong2 b = my_zpu[((w2 * 4 + bp) * 2 + 1) * 32 + jj];
                s0 = add2_(s0, a.x); s1 = add2_(s1, a.y);
                s2 = add2_(s2, b.x); s3 = add2_(s3, b.y);
            }
            float2 zi = unpk2(s0), zf = unpk2(s1), zg = unpk2(s2), zo = unpk2(s3);
            float i0 = siga(zi.x + x[0]), f0 = siga(zf.x + x[1]);
            float g0 = tanha(zg.x + x[2]), o0 = siga(zo.x + x[3]);
            float i1 = siga(zi.y + x[4]), f1 = siga(zf.y + x[5]);
            float g1 = tanha(zg.y + x[6]), o1 = siga(zo.y + x[7]);
            cst0 = f0 * cst0 + i0 * g0;
            cst1 = f1 * cst1 + i1 * g1;
            float h0new = o0 * tanha(cst0);
            float h1new = o1 * tanha(cst1);
            my_stg[bp * 32 + jj] = pk2(h0new, h1new);   // lane-stride 8B, CF

            // consumer barrier: stg/zpu-reads done before bulk issue
            if (grp) asm volatile("bar.sync 4, 128;" ::: "memory");
            else     asm volatile("bar.sync 3, 128;" ::: "memory");

            if (issuer && n < 511) {
                asm volatile("fence.proxy.async.shared::cta;" ::: "memory");
#pragma unroll
                for (int p = 0; p < 4; p++) {
                    uint32_t dst = rdst + (uint32_t)(((nxt * 4 + p) * 256 + rank * 32) * 8);
                    uint32_t src = stg_src + (uint32_t)(p * 256);
                    asm volatile(
                        "cp.async.bulk.shared::cluster.shared::cta.mbarrier::complete_tx::bytes "
                        "[%0], [%1], %2, [%3];"
                        :: "r"(dst), "r"(src), "r"(256u), "r"(rmbar + nxt * 8)
                        : "memory");
                }
            }
            // off the critical path: global h stores
            hout[((size_t)b0 * 512 + t) * 256 + rank * 32 + jj] = h0new;
            hout[((size_t)b1 * 512 + t) * 256 + rank * 32 + jj] = h1new;
        }
    }
}

// ---------------------------------------------------------------------------
// K3: logits = [h_fwd ; h_bwd] @ W_d + b_d.  Warp per row, W_d^T in smem.
// ---------------------------------------------------------------------------
__global__ void k_logits(const float* __restrict__ Wd, const float* __restrict__ bd,
                         float* __restrict__ out)
{
    __shared__ float Wds[NTAGS_ * 512];
    __shared__ float bds[NTAGS_];
    int tid = threadIdx.x;
    for (int i = tid; i < 512 * NTAGS_; i += 256) {
        int k = i / NTAGS_, c = i - k * NTAGS_;
        Wds[c * 512 + k] = Wd[i];
    }
    if (tid < NTAGS_) bds[tid] = bd[tid];
    __syncthreads();

    int wid = tid >> 5, l = tid & 31;
    int r = blockIdx.x * 8 + wid;
    const float* pf = g_hf + (size_t)r * 256 + l;
    const float* pb = g_hb + (size_t)r * 256 + l;
    float hf[8], hbv[8];
#pragma unroll
    for (int i = 0; i < 8; i++) { hf[i] = pf[32 * i]; hbv[i] = pb[32 * i]; }

    float parts[NTAGS_];
#pragma unroll
    for (int c = 0; c < NTAGS_; c++) {
        float p = 0.f;
#pragma unroll
        for (int i = 0; i < 8; i++) {
            p = fmaf(hf[i],  Wds[c * 512 + 32 * i + l], p);
            p = fmaf(hbv[i], Wds[c * 512 + 256 + 32 * i + l], p);
        }
        parts[c] = p;
    }
#pragma unroll
    for (int c = 0; c < NTAGS_; c++)
#pragma unroll
        for (int off = 16; off; off >>= 1)
            parts[c] += __shfl_xor_sync(0xffffffffu, parts[c], off);

    if (l == 0) {
#pragma unroll
        for (int c = 0; c < NTAGS_; c++)
            out[(size_t)r * NTAGS_ + c] = parts[c] + bds[c];
    }
}

// ---------------------------------------------------------------------------
// K4: lens + CRF.  One warp per batch element; fast-math exp/log.
// ---------------------------------------------------------------------------
__global__ void k_crf(const int* __restrict__ text, const int* __restrict__ labels,
                      const float* __restrict__ trans, float* __restrict__ out)
{
    int b = blockIdx.x;
    int l = threadIdx.x;
    const float* lgb = out + (size_t)b * NS_ * NTAGS_;
    const int*   lab = labels + b * NS_;

    int cnt = 0;
#pragma unroll
    for (int i = 0; i < 16; i++) cnt += (text[b * NS_ + l + 32 * i] != 0) ? 1 : 0;
#pragma unroll
    for (int off = 16; off; off >>= 1) cnt += __shfl_xor_sync(0xffffffffu, cnt, off);
    int len = cnt;
    if (l == 0) out[LENS_OFF + b] = (float)len;

    float sc = 0.f;
#pragma unroll
    for (int i = 0; i < 16; i++) {
        int s = l + 32 * i;
        if (s < len)     sc += lgb[s * NTAGS_ + lab[s]];
        if (s < len - 1) sc += trans[lab[s] * NTAGS_ + lab[s + 1]];
    }
#pragma unroll
    for (int off = 16; off; off >>= 1) sc += __shfl_xor_sync(0xffffffffu, sc, off);

    int j = l;
    float tc[NTAGS_];
#pragma unroll
    for (int i = 0; i < NTAGS_; i++) tc[i] = trans[i * NTAGS_ + ((j < NTAGS_) ? j : 0)];
    float alpha = (j < NTAGS_) ? lgb[j] : -3.0e38f;

    float lt_next = (j < NTAGS_) ? lgb[NTAGS_ + j] : 0.f;
    for (int t = 1; t < NS_; t++) {
        float lt = lt_next;
        if (t + 1 < NS_) lt_next = (j < NTAGS_) ? lgb[(t + 1) * NTAGS_ + j] : 0.f;
        float vv[NTAGS_];
#pragma unroll
        for (int i = 0; i < NTAGS_; i++) {
            float ai = __shfl_sync(0xffffffffu, alpha, i);
            vv[i] = ai + tc[i];
        }
        float m01 = fmaxf(vv[0], vv[1]), m23 = fmaxf(vv[2], vv[3]);
        float m45 = fmaxf(vv[4], vv[5]), m67 = fmaxf(vv[6], vv[7]);
        float m03 = fmaxf(m01, m23), m47 = fmaxf(m45, m67);
        float mx = fmaxf(fmaxf(m03, m47), vv[8]);
        float e0 = __expf(vv[0] - mx) + __expf(vv[1] - mx);
        float e1 = __expf(vv[2] - mx) + __expf(vv[3] - mx);
        float e2 = __expf(vv[4] - mx) + __expf(vv[5] - mx);
        float e3 = __expf(vv[6] - mx) + __expf(vv[7] - mx);
        float sume = ((e0 + e1) + (e2 + e3)) + __expf(vv[8] - mx);
        float na = mx + __logf(sume) + lt;
        if ((t < len) && (j < NTAGS_)) alpha = na;
    }

    float a = (j < NTAGS_) ? alpha : -3.0e38f;
    float mx = a;
#pragma unroll
    for (int off = 16; off; off >>= 1) mx = fmaxf(mx, __shfl_xor_sync(0xffffffffu, mx, off));
    float e = (j < NTAGS_) ? __expf(a - mx) : 0.f;
#pragma unroll
    for (int off = 16; off; off >>= 1) e += __shfl_xor_sync(0xffffffffu, e, off);
    float lse = mx + __logf(e);

    if (l == 0) out[LL_OFF + b] = sc - lse;
}

// ---------------------------------------------------------------------------
extern "C" void kernel_launch(void* const* d_in, const int* in_sizes, int n_in,
                              void* d_out, int out_size)
{
    (void)in_sizes; (void)n_in; (void)out_size;
    const int*   text   = (const int*)d_in[0];
    const int*   labels = (const int*)d_in[1];
    const float* emb    = (const float*)d_in[2];
    const float* Wf     = (const float*)d_in[3];
    const float* Uf     = (const float*)d_in[4];
    const float* bf     = (const float*)d_in[5];
    const float* Wb     = (const float*)d_in[6];
    const float* Ub     = (const float*)d_in[7];
    const float* bb     = (const float*)d_in[8];
    const float* Wd     = (const float*)d_in[9];
    const float* bd     = (const float*)d_in[10];
    const float* trans  = (const float*)d_in[11];
    float* out = (float*)d_out;

    int smem1 = 64 * 130 * 8 + 128 * 64 * 4 + 64 * 4;               // 99584 B
    cudaFuncSetAttribute(k_ingemm, cudaFuncAttributeMaxDynamicSharedMemorySize, smem1);
    // Uc 131072 + hbu 32768 + zpu 65536 + stg 2048 + mbar 32 = 231456 B
    int smem2 = 131072 + 32768 + 65536 + 2048 + 32;
    cudaFuncSetAttribute(k_lstm, cudaFuncAttributeMaxDynamicSharedMemorySize, smem2);

    k_ingemm<<<dim3(512, 32), 256, smem1>>>(text, emb, Wf, bf, Wb, bb);
    // dummies keep the ncu capture slot (-s 5 -c 1) on k_lstm
    k_nop<<<1, 32>>>(0);
    k_nop<<<1, 32>>>(1);
    k_lstm<<<64, 512, smem2>>>(Uf, Ub);
    k_logits<<<4096, 256>>>(Wd, bd, out);
    k_crf<<<NB_, 32>>>(text, labels, trans, out);
}